// round 4
// baseline (speedup 1.0000x reference)
#include <cuda_runtime.h>
#include <cuda_bf16.h>
#include <math.h>

#define HN   24
#define DHD  128
#define TXT_ 512
#define IMG_ 1024
#define SALL 1536
#define HID_ 3072
#define IPD_ 1152
#define IPL_ 128

// ---------------- static scratch (allocation-free) ----------------
// fp32 intermediates
__device__ float g_q[IMG_ * HID_];
__device__ float g_k[IMG_ * HID_];
__device__ float g_v[IMG_ * HID_];
__device__ float g_eq[TXT_ * HID_];
__device__ float g_ek[TXT_ * HID_];
__device__ float g_ev[TXT_ * HID_];
__device__ float g_ipk[IPL_ * HID_];
__device__ float g_ipv[IPL_ * HID_];
__device__ float g_S[HN * SALL * SALL];
__device__ float g_Sip[HN * IMG_ * IPL_];
__device__ float g_O[HN * SALL * DHD];
__device__ float g_ipO[HN * IMG_ * DHD];
// packed (bf16 hi/lo pairs) GEMM operands
__device__ uint2 g_hp[IMG_ * HID_ / 2];
__device__ uint2 g_ep[TXT_ * HID_ / 2];
__device__ uint2 g_ipp[IPL_ * IPD_ / 2];
__device__ uint2 g_Wq_p[HID_ * HID_ / 2];
__device__ uint2 g_Wk_p[HID_ * HID_ / 2];
__device__ uint2 g_Wv_p[HID_ * HID_ / 2];
__device__ uint2 g_Wqa_p[HID_ * HID_ / 2];
__device__ uint2 g_Wka_p[HID_ * HID_ / 2];
__device__ uint2 g_Wva_p[HID_ * HID_ / 2];
__device__ uint2 g_Wo_p[HID_ * HID_ / 2];
__device__ uint2 g_Wao_p[HID_ * HID_ / 2];
__device__ uint2 g_Wkip_p[HID_ * IPD_ / 2];
__device__ uint2 g_Wvip_p[HID_ * IPD_ / 2];
__device__ uint2 g_qfp[HN * SALL * DHD / 2];
__device__ uint2 g_kfp[HN * SALL * DHD / 2];
__device__ uint2 g_vtp[HN * DHD * SALL / 2];
__device__ uint2 g_ipqp[HN * IMG_ * DHD / 2];
__device__ uint2 g_ipkhp[HN * IPL_ * DHD / 2];
__device__ uint2 g_ipvtp[HN * DHD * IPL_ / 2];
__device__ uint2 g_Pp[HN * SALL * SALL / 2];
__device__ uint2 g_Sipp[HN * IMG_ * IPL_ / 2];
__device__ uint2 g_imgp[IMG_ * HID_ / 2];
__device__ uint2 g_encp[TXT_ * HID_ / 2];

// ---------------- bf16 hi/lo split helpers ----------------
__device__ __forceinline__ uint2 pack2(float f0, float f1) {
    __nv_bfloat16 h0 = __float2bfloat16(f0);
    __nv_bfloat16 h1 = __float2bfloat16(f1);
    __nv_bfloat16 l0 = __float2bfloat16(f0 - __bfloat162float(h0));
    __nv_bfloat16 l1 = __float2bfloat16(f1 - __bfloat162float(h1));
    uint2 u;
    u.x = (unsigned)__bfloat16_as_ushort(h0) | ((unsigned)__bfloat16_as_ushort(h1) << 16);
    u.y = (unsigned)__bfloat16_as_ushort(l0) | ((unsigned)__bfloat16_as_ushort(l1) << 16);
    return u;
}

__device__ __forceinline__ void mma_bf16(float* d, const unsigned* a, const unsigned* b) {
    asm volatile(
        "mma.sync.aligned.m16n8k16.row.col.f32.bf16.bf16.f32 "
        "{%0,%1,%2,%3}, {%4,%5,%6,%7}, {%8,%9}, {%0,%1,%2,%3};"
        : "+f"(d[0]), "+f"(d[1]), "+f"(d[2]), "+f"(d[3])
        : "r"(a[0]), "r"(a[1]), "r"(a[2]), "r"(a[3]), "r"(b[0]), "r"(b[1]));
}

// smem pair index with xor swizzle: row r, pair e (0..15)
__device__ __forceinline__ int sidx(int r, int e) {
    return r * 16 + (e ^ ((r & 3) << 2));
}

// ---------------- pack kernel: fp32 -> (bf16hi,bf16lo) pairs ----------------
__global__ void pack_mat(const float* __restrict__ src, uint2* __restrict__ dst, int n4) {
    int i = blockIdx.x * 256 + threadIdx.x;
    if (i < n4) {
        float4 f = ((const float4*)src)[i];
        uint2 a = pack2(f.x, f.y);
        uint2 b = pack2(f.z, f.w);
        uint4 o;
        o.x = a.x; o.y = a.y; o.z = b.x; o.w = b.y;
        ((uint4*)dst)[i] = o;
    }
}

// ---------------- bf16x3 tensor-core GEMM (NT, packed operands) ------------
// C[M,N] = A[M,K] * B[N,K]^T + bias.  A,B packed as uint2 pairs (Kp = K/2).
// BM=128, BN=128, BK=32 (16 pairs), 256 threads, 8 warps (4x2), warp 32x64.
__global__ __launch_bounds__(256) void gemm_tc(
    const uint2* __restrict__ A, const uint2* __restrict__ B,
    const float* __restrict__ bias, float* __restrict__ C,
    int M, int N, int Kp,
    long long sA, long long sB, long long sC)
{
    A += (long long)blockIdx.z * sA;
    B += (long long)blockIdx.z * sB;
    C += (long long)blockIdx.z * sC;

    __shared__ uint2 As[128 * 16];   // 16 KB
    __shared__ uint2 Bs[128 * 16];   // 16 KB

    int tid = threadIdx.x;
    int warp = tid >> 5, lane = tid & 31;
    int wm = warp >> 1, wn = warp & 1;
    int m0 = blockIdx.y * 128, n0 = blockIdx.x * 128;
    int g = lane >> 2, t = lane & 3;

    float acc[2][8][4];
#pragma unroll
    for (int mt = 0; mt < 2; mt++)
#pragma unroll
        for (int nt = 0; nt < 8; nt++)
#pragma unroll
            for (int i = 0; i < 4; i++) acc[mt][nt][i] = 0.f;

    int nkt = Kp >> 4;
    uint4 pa[4], pb[4];

    int lrow = tid >> 3;          // 0..31 (+32*it)
    int lq = (tid & 7) << 1;      // pair offset 0,2,..,14

#pragma unroll
    for (int it = 0; it < 4; it++) {
        int row = lrow + it * 32;
        pa[it] = *(const uint4*)(A + (long long)(m0 + row) * Kp + lq);
        pb[it] = *(const uint4*)(B + (long long)(n0 + row) * Kp + lq);
    }
#pragma unroll
    for (int it = 0; it < 4; it++) {
        int row = lrow + it * 32;
        *(uint4*)&As[sidx(row, lq)] = pa[it];
        *(uint4*)&Bs[sidx(row, lq)] = pb[it];
    }
    __syncthreads();

    for (int kt = 0; kt < nkt; kt++) {
        if (kt + 1 < nkt) {
            int kb = (kt + 1) << 4;
#pragma unroll
            for (int it = 0; it < 4; it++) {
                int row = lrow + it * 32;
                pa[it] = *(const uint4*)(A + (long long)(m0 + row) * Kp + kb + lq);
                pb[it] = *(const uint4*)(B + (long long)(n0 + row) * Kp + kb + lq);
            }
        }

#pragma unroll
        for (int kc = 0; kc < 2; kc++) {
            int e0 = kc * 8 + t;
            unsigned ah[2][4], al[2][4];
#pragma unroll
            for (int mt = 0; mt < 2; mt++) {
                int mr = wm * 32 + mt * 16 + g;
                uint2 u0 = As[sidx(mr, e0)];
                uint2 u1 = As[sidx(mr + 8, e0)];
                uint2 u2 = As[sidx(mr, e0 + 4)];
                uint2 u3 = As[sidx(mr + 8, e0 + 4)];
                ah[mt][0] = u0.x; al[mt][0] = u0.y;
                ah[mt][1] = u1.x; al[mt][1] = u1.y;
                ah[mt][2] = u2.x; al[mt][2] = u2.y;
                ah[mt][3] = u3.x; al[mt][3] = u3.y;
            }
#pragma unroll
            for (int nt = 0; nt < 8; nt++) {
                int nr = wn * 64 + nt * 8 + g;
                uint2 v0 = Bs[sidx(nr, e0)];
                uint2 v1 = Bs[sidx(nr, e0 + 4)];
                unsigned bh[2] = { v0.x, v1.x };
                unsigned bl[2] = { v0.y, v1.y };
#pragma unroll
                for (int mt = 0; mt < 2; mt++) {
                    mma_bf16(acc[mt][nt], ah[mt], bh);
                    mma_bf16(acc[mt][nt], ah[mt], bl);
                    mma_bf16(acc[mt][nt], al[mt], bh);
                }
            }
        }
        __syncthreads();
        if (kt + 1 < nkt) {
#pragma unroll
            for (int it = 0; it < 4; it++) {
                int row = lrow + it * 32;
                *(uint4*)&As[sidx(row, lq)] = pa[it];
                *(uint4*)&Bs[sidx(row, lq)] = pb[it];
            }
            __syncthreads();
        }
    }

#pragma unroll
    for (int nt = 0; nt < 8; nt++) {
        int ncol = n0 + wn * 64 + nt * 8 + t * 2;
        float2 bv;
        if (bias) bv = *(const float2*)(bias + ncol);
        else { bv.x = 0.f; bv.y = 0.f; }
#pragma unroll
        for (int mt = 0; mt < 2; mt++) {
            int mrow = m0 + wm * 32 + mt * 16 + g;
            float2 v0, v1;
            v0.x = acc[mt][nt][0] + bv.x; v0.y = acc[mt][nt][1] + bv.y;
            v1.x = acc[mt][nt][2] + bv.x; v1.y = acc[mt][nt][3] + bv.y;
            *(float2*)(C + (long long)mrow * N + ncol) = v0;
            *(float2*)(C + (long long)(mrow + 8) * N + ncol) = v1;
        }
    }
}

// ---------------- heads + RMS + RoPE -> packed dst ----------------
__global__ void build_qk_rope(const float* __restrict__ enc_lin,
                              const float* __restrict__ img_lin,
                              const float* __restrict__ w_enc,
                              const float* __restrict__ w_img,
                              const float* __restrict__ cosb,
                              const float* __restrict__ sinb,
                              uint2* __restrict__ dstp)
{
    int s = blockIdx.x;
    int h = blockIdx.y;
    int d = threadIdx.x;
    const float* src;
    const float* w;
    if (s < TXT_) { src = enc_lin + (long long)s * HID_; w = w_enc; }
    else          { src = img_lin + (long long)(s - TXT_) * HID_; w = w_img; }
    float x = src[h * DHD + d];
    float ss = x * x;
#pragma unroll
    for (int o = 16; o; o >>= 1) ss += __shfl_xor_sync(0xffffffffu, ss, o);
    __shared__ float sred[4];
    int lane = d & 31, wid = d >> 5;
    if (lane == 0) sred[wid] = ss;
    __syncthreads();
    ss = sred[0] + sred[1] + sred[2] + sred[3];
    float r = rsqrtf(ss * (1.0f / DHD) + 1e-6f);
    float xn = x * r * w[d];
    float partner = __shfl_xor_sync(0xffffffffu, xn, 1);
    float rot = (d & 1) ? partner : -partner;
    long long si = (long long)s * DHD + d;
    float res = xn * cosb[si] + rot * sinb[si];
    float res1 = __shfl_down_sync(0xffffffffu, res, 1);
    if (!(d & 1))
        dstp[(((long long)h * SALL + s) * DHD + d) >> 1] = pack2(res, res1);
}

// rms -> packed dst[h][s][d-pairs]
__global__ void build_rms(const float* __restrict__ src, const float* __restrict__ w,
                          uint2* __restrict__ dstp, int Srows)
{
    int s = blockIdx.x;
    int h = blockIdx.y;
    int d = threadIdx.x;
    float x = src[(long long)s * HID_ + h * DHD + d];
    float ss = x * x;
#pragma unroll
    for (int o = 16; o; o >>= 1) ss += __shfl_xor_sync(0xffffffffu, ss, o);
    __shared__ float sred[4];
    int lane = d & 31, wid = d >> 5;
    if (lane == 0) sred[wid] = ss;
    __syncthreads();
    ss = sred[0] + sred[1] + sred[2] + sred[3];
    float r = rsqrtf(ss * (1.0f / DHD) + 1e-6f);
    float res = x * r * w[d];
    float res1 = __shfl_down_sync(0xffffffffu, res, 1);
    if (!(d & 1))
        dstp[(((long long)h * Srows + s) * DHD + d) >> 1] = pack2(res, res1);
}

// transpose to packed dst[h][d][s-pairs]. block (32,8), grid (S/32, DHD/32, HN)
__global__ void transpose_heads_p(const float* __restrict__ enc, const float* __restrict__ img,
                                  int ntxt, uint2* __restrict__ dst, int Srows)
{
    __shared__ float tbuf[32][33];
    int s0 = blockIdx.x * 32, d0 = blockIdx.y * 32, h = blockIdx.z;
    int tx = threadIdx.x, ty = threadIdx.y;
#pragma unroll
    for (int j = 0; j < 4; j++) {
        int s = s0 + ty + j * 8;
        const float* src = (s < ntxt) ? enc + (long long)s * HID_
                                      : img + (long long)(s - ntxt) * HID_;
        tbuf[ty + j * 8][tx] = src[h * DHD + d0 + tx];
    }
    __syncthreads();
    int Sp = Srows >> 1;
    if (tx < 16) {
#pragma unroll
        for (int j = 0; j < 4; j++) {
            int dl = ty + j * 8;
            int d = d0 + dl;
            float a = tbuf[2 * tx][dl];
            float b = tbuf[2 * tx + 1][dl];
            dst[((long long)h * DHD + d) * Sp + (s0 >> 1) + tx] = pack2(a, b);
        }
    }
}

// ---------------- softmax: fp32 in -> packed probabilities out --------------
__global__ void softmax_p(const float* __restrict__ S, uint2* __restrict__ P,
                          int ncols, float scale)
{
    long long row = blockIdx.x;
    const float* src = S + row * (long long)ncols;
    uint2* dst = P + row * (long long)(ncols >> 1);
    int tid = threadIdx.x;
    int np = ncols >> 1;
    float2 lv[3];
    int cnt = 0;
    float mx = -INFINITY;
    for (int j = tid; j < np; j += 256) {
        float2 v = ((const float2*)src)[j];
        v.x *= scale; v.y *= scale;
        lv[cnt++] = v;
        mx = fmaxf(mx, fmaxf(v.x, v.y));
    }
    __shared__ float sred[8];
    int lane = tid & 31, wid = tid >> 5;
#pragma unroll
    for (int o = 16; o; o >>= 1) mx = fmaxf(mx, __shfl_xor_sync(0xffffffffu, mx, o));
    if (lane == 0) sred[wid] = mx;
    __syncthreads();
    mx = sred[0];
#pragma unroll
    for (int i = 1; i < 8; i++) mx = fmaxf(mx, sred[i]);
    __syncthreads();
    float sum = 0.f;
    for (int c = 0; c < cnt; c++) {
        lv[c].x = expf(lv[c].x - mx);
        lv[c].y = expf(lv[c].y - mx);
        sum += lv[c].x + lv[c].y;
    }
#pragma unroll
    for (int o = 16; o; o >>= 1) sum += __shfl_xor_sync(0xffffffffu, sum, o);
    if (lane == 0) sred[wid] = sum;
    __syncthreads();
    sum = sred[0];
#pragma unroll
    for (int i = 1; i < 8; i++) sum += sred[i];
    float inv = 1.0f / sum;
    cnt = 0;
    for (int j = tid; j < np; j += 256) {
        dst[j] = pack2(lv[cnt].x * inv, lv[cnt].y * inv);
        cnt++;
    }
}

// ---------------- merge + bbox mask -> packed ----------------
__global__ void merge_img_p(const float* __restrict__ O, const float* __restrict__ ipO,
                            uint2* __restrict__ dstp)
{
    int l = blockIdx.x, h = blockIdx.y, d = threadIdx.x;
    int row = l >> 5, col = l & 31;
    float m = (row >= 8 && row < 24 && col >= 8 && col < 24) ? 1.0f : 0.0f;
    float res = O[((long long)h * SALL + TXT_ + l) * DHD + d] +
                m * ipO[((long long)h * IMG_ + l) * DHD + d];
    float res1 = __shfl_down_sync(0xffffffffu, res, 1);
    if (!(d & 1))
        dstp[((long long)l * HID_ + h * DHD + d) >> 1] = pack2(res, res1);
}

__global__ void merge_enc_p(const float* __restrict__ O, uint2* __restrict__ dstp)
{
    int s = blockIdx.x, h = blockIdx.y, d = threadIdx.x;
    float res = O[((long long)h * SALL + s) * DHD + d];
    float res1 = __shfl_down_sync(0xffffffffu, res, 1);
    if (!(d & 1))
        dstp[((long long)s * HID_ + h * DHD + d) >> 1] = pack2(res, res1);
}

// ---------------- launch ----------------
extern "C" void kernel_launch(void* const* d_in, const int* in_sizes, int n_in,
                              void* d_out, int out_size)
{
    const float* hidden   = (const float*)d_in[0];
    const float* enc_hs   = (const float*)d_in[1];
    const float* ip_hs    = (const float*)d_in[2];
    const float* rope_cos = (const float*)d_in[3];
    const float* rope_sin = (const float*)d_in[4];
    const float* Wq  = (const float*)d_in[5];
    const float* bq  = (const float*)d_in[6];
    const float* Wk  = (const float*)d_in[7];
    const float* bk  = (const float*)d_in[8];
    const float* Wv  = (const float*)d_in[9];
    const float* bv  = (const float*)d_in[10];
    const float* norm_q_w = (const float*)d_in[11];
    const float* norm_k_w = (const float*)d_in[12];
    const float* Wq_add = (const float*)d_in[13];
    const float* bq_add = (const float*)d_in[14];
    const float* Wk_add = (const float*)d_in[15];
    const float* bk_add = (const float*)d_in[16];
    const float* Wv_add = (const float*)d_in[17];
    const float* bv_add = (const float*)d_in[18];
    const float* norm_added_q_w = (const float*)d_in[19];
    const float* norm_added_k_w = (const float*)d_in[20];
    const float* W_out = (const float*)d_in[21];
    const float* b_out = (const float*)d_in[22];
    const float* W_add_out = (const float*)d_in[23];
    const float* b_add_out = (const float*)d_in[24];
    const float* W_k_ip = (const float*)d_in[25];
    const float* b_k_ip = (const float*)d_in[26];
    const float* W_v_ip = (const float*)d_in[27];
    const float* b_v_ip = (const float*)d_in[28];
    const float* norm_ip_q_w = (const float*)d_in[29];
    const float* norm_ip_k_w = (const float*)d_in[30];

    float* out_img = (float*)d_out;
    float* out_enc = out_img + (size_t)IMG_ * HID_;

    float *q, *k, *v, *eq, *ek, *ev, *ipk, *ipv, *Sb, *Sip, *O, *ipO;
    uint2 *hp, *ep, *ipp, *Wqp, *Wkp, *Wvp, *Wqap, *Wkap, *Wvap, *Wop, *Waop, *Wkipp, *Wvipp;
    uint2 *qfp, *kfp, *vtp, *ipqp, *ipkhp, *ipvtp, *Pp, *Sipp, *imgp, *encp;
    cudaGetSymbolAddress((void**)&q, g_q);
    cudaGetSymbolAddress((void**)&k, g_k);
    cudaGetSymbolAddress((void**)&v, g_v);
    cudaGetSymbolAddress((void**)&eq, g_eq);
    cudaGetSymbolAddress((void**)&ek, g_ek);
    cudaGetSymbolAddress((void**)&ev, g_ev);
    cudaGetSymbolAddress((void**)&ipk, g_ipk);
    cudaGetSymbolAddress((void**)&ipv, g_ipv);
    cudaGetSymbolAddress((void**)&Sb, g_S);
    cudaGetSymbolAddress((void**)&Sip, g_Sip);
    cudaGetSymbolAddress((void**)&O, g_O);
    cudaGetSymbolAddress((void**)&ipO, g_ipO);
    cudaGetSymbolAddress((void**)&hp, g_hp);
    cudaGetSymbolAddress((void**)&ep, g_ep);
    cudaGetSymbolAddress((void**)&ipp, g_ipp);
    cudaGetSymbolAddress((void**)&Wqp, g_Wq_p);
    cudaGetSymbolAddress((void**)&Wkp, g_Wk_p);
    cudaGetSymbolAddress((void**)&Wvp, g_Wv_p);
    cudaGetSymbolAddress((void**)&Wqap, g_Wqa_p);
    cudaGetSymbolAddress((void**)&Wkap, g_Wka_p);
    cudaGetSymbolAddress((void**)&Wvap, g_Wva_p);
    cudaGetSymbolAddress((void**)&Wop, g_Wo_p);
    cudaGetSymbolAddress((void**)&Waop, g_Wao_p);
    cudaGetSymbolAddress((void**)&Wkipp, g_Wkip_p);
    cudaGetSymbolAddress((void**)&Wvipp, g_Wvip_p);
    cudaGetSymbolAddress((void**)&qfp, g_qfp);
    cudaGetSymbolAddress((void**)&kfp, g_kfp);
    cudaGetSymbolAddress((void**)&vtp, g_vtp);
    cudaGetSymbolAddress((void**)&ipqp, g_ipqp);
    cudaGetSymbolAddress((void**)&ipkhp, g_ipkhp);
    cudaGetSymbolAddress((void**)&ipvtp, g_ipvtp);
    cudaGetSymbolAddress((void**)&Pp, g_Pp);
    cudaGetSymbolAddress((void**)&Sipp, g_Sipp);
    cudaGetSymbolAddress((void**)&imgp, g_imgp);
    cudaGetSymbolAddress((void**)&encp, g_encp);

    const float scale = 0.08838834764831845f; // 1/sqrt(128)

    // --- pack inputs & weights ---
    const int WW4 = HID_ * HID_ / 4, WIP4 = HID_ * IPD_ / 4;
    pack_mat<<<(IMG_ * HID_ / 4 + 255) / 256, 256>>>(hidden, hp, IMG_ * HID_ / 4);
    pack_mat<<<(TXT_ * HID_ / 4 + 255) / 256, 256>>>(enc_hs, ep, TXT_ * HID_ / 4);
    pack_mat<<<(IPL_ * IPD_ / 4 + 255) / 256, 256>>>(ip_hs, ipp, IPL_ * IPD_ / 4);
    pack_mat<<<(WW4 + 255) / 256, 256>>>(Wq, Wqp, WW4);
    pack_mat<<<(WW4 + 255) / 256, 256>>>(Wk, Wkp, WW4);
    pack_mat<<<(WW4 + 255) / 256, 256>>>(Wv, Wvp, WW4);
    pack_mat<<<(WW4 + 255) / 256, 256>>>(Wq_add, Wqap, WW4);
    pack_mat<<<(WW4 + 255) / 256, 256>>>(Wk_add, Wkap, WW4);
    pack_mat<<<(WW4 + 255) / 256, 256>>>(Wv_add, Wvap, WW4);
    pack_mat<<<(WW4 + 255) / 256, 256>>>(W_out, Wop, WW4);
    pack_mat<<<(WW4 + 255) / 256, 256>>>(W_add_out, Waop, WW4);
    pack_mat<<<(WIP4 + 255) / 256, 256>>>(W_k_ip, Wkipp, WIP4);
    pack_mat<<<(WIP4 + 255) / 256, 256>>>(W_v_ip, Wvipp, WIP4);

    const int HIDp = HID_ / 2, IPDp = IPD_ / 2, DHp = DHD / 2, SAp = SALL / 2, IPLp = IPL_ / 2;

    // --- projections ---
    gemm_tc<<<dim3(HID_ / 128, IMG_ / 128), 256>>>(hp, Wqp, bq, q, IMG_, HID_, HIDp, 0, 0, 0);
    gemm_tc<<<dim3(HID_ / 128, IMG_ / 128), 256>>>(hp, Wkp, bk, k, IMG_, HID_, HIDp, 0, 0, 0);
    gemm_tc<<<dim3(HID_ / 128, IMG_ / 128), 256>>>(hp, Wvp, bv, v, IMG_, HID_, HIDp, 0, 0, 0);
    gemm_tc<<<dim3(HID_ / 128, TXT_ / 128), 256>>>(ep, Wqap, bq_add, eq, TXT_, HID_, HIDp, 0, 0, 0);
    gemm_tc<<<dim3(HID_ / 128, TXT_ / 128), 256>>>(ep, Wkap, bk_add, ek, TXT_, HID_, HIDp, 0, 0, 0);
    gemm_tc<<<dim3(HID_ / 128, TXT_ / 128), 256>>>(ep, Wvap, bv_add, ev, TXT_, HID_, HIDp, 0, 0, 0);
    gemm_tc<<<dim3(HID_ / 128, IPL_ / 128), 256>>>(ipp, Wkipp, b_k_ip, ipk, IPL_, HID_, IPDp, 0, 0, 0);
    gemm_tc<<<dim3(HID_ / 128, IPL_ / 128), 256>>>(ipp, Wvipp, b_v_ip, ipv, IPL_, HID_, IPDp, 0, 0, 0);

    // --- heads / rms / rope / transposes (write packed) ---
    build_qk_rope<<<dim3(SALL, HN), 128>>>(eq, q, norm_added_q_w, norm_q_w, rope_cos, rope_sin, qfp);
    build_qk_rope<<<dim3(SALL, HN), 128>>>(ek, k, norm_added_k_w, norm_k_w, rope_cos, rope_sin, kfp);
    transpose_heads_p<<<dim3(SALL / 32, DHD / 32, HN), dim3(32, 8)>>>(ev, v, TXT_, vtp, SALL);
    build_rms<<<dim3(IMG_, HN), 128>>>(q, norm_ip_q_w, ipqp, IMG_);
    build_rms<<<dim3(IPL_, HN), 128>>>(ipk, norm_ip_k_w, ipkhp, IPL_);
    transpose_heads_p<<<dim3(IPL_ / 32, DHD / 32, HN), dim3(32, 8)>>>(ipv, ipv, IPL_, ipvtp, IPL_);

    // --- main attention ---
    gemm_tc<<<dim3(SALL / 128, SALL / 128, HN), 256>>>(
        qfp, kfp, nullptr, Sb, SALL, SALL, DHp,
        (long long)SALL * DHp, (long long)SALL * DHp, (long long)SALL * SALL);
    softmax_p<<<HN * SALL, 256>>>(Sb, Pp, SALL, scale);
    gemm_tc<<<dim3(DHD / 128, SALL / 128, HN), 256>>>(
        Pp, vtp, nullptr, O, SALL, DHD, SAp,
        (long long)SALL * SAp, (long long)DHD * SAp, (long long)SALL * DHD);

    // --- ip attention ---
    gemm_tc<<<dim3(IPL_ / 128, IMG_ / 128, HN), 256>>>(
        ipqp, ipkhp, nullptr, Sip, IMG_, IPL_, DHp,
        (long long)IMG_ * DHp, (long long)IPL_ * DHp, (long long)IMG_ * IPL_);
    softmax_p<<<HN * IMG_, 256>>>(Sip, Sipp, IPL_, scale);
    gemm_tc<<<dim3(DHD / 128, IMG_ / 128, HN), 256>>>(
        Sipp, ipvtp, nullptr, ipO, IMG_, DHD, IPLp,
        (long long)IMG_ * IPLp, (long long)DHD * IPLp, (long long)IMG_ * DHD);

    // --- merge + output projections ---
    merge_img_p<<<dim3(IMG_, HN), 128>>>(O, ipO, imgp);
    merge_enc_p<<<dim3(TXT_, HN), 128>>>(O, encp);
    gemm_tc<<<dim3(HID_ / 128, IMG_ / 128), 256>>>(imgp, Wop, b_out, out_img, IMG_, HID_, HIDp, 0, 0, 0);
    gemm_tc<<<dim3(HID_ / 128, TXT_ / 128), 256>>>(encp, Waop, b_add_out, out_enc, TXT_, HID_, HIDp, 0, 0, 0);
}

// round 6
// speedup vs baseline: 1.3207x; 1.3207x over previous
#include <cuda_runtime.h>
#include <cuda_bf16.h>
#include <math.h>
#include <stdint.h>

#define HN   24
#define DHD  128
#define TXT_ 512
#define IMG_ 1024
#define SALL 1536
#define HID_ 3072
#define IPD_ 1152
#define IPL_ 128

// ---------------- static scratch (allocation-free) ----------------
__device__ float g_q[IMG_ * HID_];
__device__ float g_k[IMG_ * HID_];
__device__ float g_v[IMG_ * HID_];
__device__ float g_eq[TXT_ * HID_];
__device__ float g_ek[TXT_ * HID_];
__device__ float g_ev[TXT_ * HID_];
__device__ float g_ipk[IPL_ * HID_];
__device__ float g_ipv[IPL_ * HID_];
__device__ float g_S[HN * SALL * SALL];
__device__ float g_Sip[HN * IMG_ * IPL_];
__device__ float g_O[HN * SALL * DHD];
__device__ float g_ipO[HN * IMG_ * DHD];
// packed (bf16 hi/lo pairs) GEMM operands
__device__ uint2 g_hp[IMG_ * HID_ / 2];
__device__ uint2 g_ep[TXT_ * HID_ / 2];
__device__ uint2 g_ipp[IPL_ * IPD_ / 2];
__device__ uint2 g_Wq_p[HID_ * HID_ / 2];
__device__ uint2 g_Wk_p[HID_ * HID_ / 2];
__device__ uint2 g_Wv_p[HID_ * HID_ / 2];
__device__ uint2 g_Wqa_p[HID_ * HID_ / 2];
__device__ uint2 g_Wka_p[HID_ * HID_ / 2];
__device__ uint2 g_Wva_p[HID_ * HID_ / 2];
__device__ uint2 g_Wo_p[HID_ * HID_ / 2];
__device__ uint2 g_Wao_p[HID_ * HID_ / 2];
__device__ uint2 g_Wkip_p[HID_ * IPD_ / 2];
__device__ uint2 g_Wvip_p[HID_ * IPD_ / 2];
__device__ uint2 g_qfp[HN * SALL * DHD / 2];
__device__ uint2 g_kfp[HN * SALL * DHD / 2];
__device__ uint2 g_vtp[HN * DHD * SALL / 2];
__device__ uint2 g_ipqp[HN * IMG_ * DHD / 2];
__device__ uint2 g_ipkhp[HN * IPL_ * DHD / 2];
__device__ uint2 g_ipvtp[HN * DHD * IPL_ / 2];
__device__ uint2 g_Pp[HN * SALL * SALL / 2];
__device__ uint2 g_Sipp[HN * IMG_ * IPL_ / 2];
__device__ uint2 g_imgp[IMG_ * HID_ / 2];
__device__ uint2 g_encp[TXT_ * HID_ / 2];

// ---------------- bf16 hi/lo split helpers ----------------
__device__ __forceinline__ uint2 pack2(float f0, float f1) {
    __nv_bfloat16 h0 = __float2bfloat16(f0);
    __nv_bfloat16 h1 = __float2bfloat16(f1);
    __nv_bfloat16 l0 = __float2bfloat16(f0 - __bfloat162float(h0));
    __nv_bfloat16 l1 = __float2bfloat16(f1 - __bfloat162float(h1));
    uint2 u;
    u.x = (unsigned)__bfloat16_as_ushort(h0) | ((unsigned)__bfloat16_as_ushort(h1) << 16);
    u.y = (unsigned)__bfloat16_as_ushort(l0) | ((unsigned)__bfloat16_as_ushort(l1) << 16);
    return u;
}

__device__ __forceinline__ void mma_bf16(float* d, const unsigned* a, const unsigned* b) {
    asm volatile(
        "mma.sync.aligned.m16n8k16.row.col.f32.bf16.bf16.f32 "
        "{%0,%1,%2,%3}, {%4,%5,%6,%7}, {%8,%9}, {%0,%1,%2,%3};"
        : "+f"(d[0]), "+f"(d[1]), "+f"(d[2]), "+f"(d[3])
        : "r"(a[0]), "r"(a[1]), "r"(a[2]), "r"(a[3]), "r"(b[0]), "r"(b[1]));
}

// smem pair index with xor swizzle: row r, pair e (0..15)
__device__ __forceinline__ int sidx(int r, int e) {
    return r * 16 + (e ^ ((r & 3) << 2));
}

__device__ __forceinline__ void cpa16(uint32_t dst, const void* src) {
    asm volatile("cp.async.cg.shared.global [%0], [%1], 16;" :: "r"(dst), "l"(src));
}
__device__ __forceinline__ void cp_commit() {
    asm volatile("cp.async.commit_group;" ::: "memory");
}
template <int NN>
__device__ __forceinline__ void cp_wait() {
    asm volatile("cp.async.wait_group %0;" :: "n"(NN) : "memory");
}

// ---------------- bf16x3 GEMM (NT, packed, cp.async 3-stage) ----------------
// C[M,N] = A[M,K] * B[N,K]^T + bias.  A,B packed uint2 (Kp = K/2).
// BM=128, BN=64, BK=32 (16 pairs), 256 threads, 8 warps (4x2), warp 32x32.
// Dynamic smem: 3 stages x (A 16KB + B 8KB) = 72 KB.
#define GST   3
#define STGB  24576
#define GSM   (GST * STGB)

__global__ __launch_bounds__(256, 2) void gemm_tc(
    const uint2* __restrict__ A, const uint2* __restrict__ B,
    const float* __restrict__ bias, float* __restrict__ C,
    int M, int N, int Kp,
    long long sA, long long sB, long long sC)
{
    A += (long long)blockIdx.z * sA;
    B += (long long)blockIdx.z * sB;
    C += (long long)blockIdx.z * sC;

    extern __shared__ __align__(16) char smem[];
    uint32_t sb = (uint32_t)__cvta_generic_to_shared(smem);

    int tid = threadIdx.x;
    int warp = tid >> 5, lane = tid & 31;
    int wm = warp >> 1, wn = warp & 1;
    int m0 = blockIdx.y * 128, n0 = blockIdx.x * 64;
    int g = lane >> 2, t = lane & 3;

    float acc[2][4][4];
#pragma unroll
    for (int mt = 0; mt < 2; mt++)
#pragma unroll
        for (int nt = 0; nt < 4; nt++)
#pragma unroll
            for (int i = 0; i < 4; i++) acc[mt][nt][i] = 0.f;

    int nkt = Kp >> 4;
    int lrow = tid >> 3;            // 0..31 (+32*it)
    int lq = (tid & 7) << 1;        // pair 0,2..14

    // stage load: A 4 txns/thread, B 2 txns/thread
#define LOAD_STAGE(kt, s)                                                              \
    {                                                                                  \
        int kb = (kt) << 4;                                                            \
        uint32_t ab = sb + (s) * STGB;                                                 \
        uint32_t bb = ab + 16384;                                                      \
        _Pragma("unroll")                                                              \
        for (int it = 0; it < 4; it++) {                                               \
            int row = lrow + it * 32;                                                  \
            cpa16(ab + sidx(row, lq) * 8, A + (long long)(m0 + row) * Kp + kb + lq);   \
        }                                                                              \
        _Pragma("unroll")                                                              \
        for (int it = 0; it < 2; it++) {                                               \
            int row = lrow + it * 32;                                                  \
            cpa16(bb + sidx(row, lq) * 8, B + (long long)(n0 + row) * Kp + kb + lq);   \
        }                                                                              \
    }

    LOAD_STAGE(0, 0);
    cp_commit();
    if (nkt > 1) { LOAD_STAGE(1, 1); }
    cp_commit();

    for (int kt = 0; kt < nkt; kt++) {
        cp_wait<1>();
        __syncthreads();
        if (kt + 2 < nkt) {
            int s = (kt + 2) % GST;
            LOAD_STAGE(kt + 2, s);
        }
        cp_commit();

        const uint2* Ap = (const uint2*)(smem + (kt % GST) * STGB);
        const uint2* Bp = (const uint2*)(smem + (kt % GST) * STGB + 16384);

#pragma unroll
        for (int kc = 0; kc < 2; kc++) {
            int e0 = kc * 8 + t;
            unsigned ah[2][4], al[2][4];
#pragma unroll
            for (int mt = 0; mt < 2; mt++) {
                int mr = wm * 32 + mt * 16 + g;
                uint2 u0 = Ap[sidx(mr, e0)];
                uint2 u1 = Ap[sidx(mr + 8, e0)];
                uint2 u2 = Ap[sidx(mr, e0 + 4)];
                uint2 u3 = Ap[sidx(mr + 8, e0 + 4)];
                ah[mt][0] = u0.x; al[mt][0] = u0.y;
                ah[mt][1] = u1.x; al[mt][1] = u1.y;
                ah[mt][2] = u2.x; al[mt][2] = u2.y;
                ah[mt][3] = u3.x; al[mt][3] = u3.y;
            }
#pragma unroll
            for (int nt = 0; nt < 4; nt++) {
                int nr = wn * 32 + nt * 8 + g;
                uint2 v0 = Bp[sidx(nr, e0)];
                uint2 v1 = Bp[sidx(nr, e0 + 4)];
                unsigned bh[2] = { v0.x, v1.x };
                unsigned bl[2] = { v0.y, v1.y };
#pragma unroll
                for (int mt = 0; mt < 2; mt++) {
                    mma_bf16(acc[mt][nt], ah[mt], bh);
                    mma_bf16(acc[mt][nt], ah[mt], bl);
                    mma_bf16(acc[mt][nt], al[mt], bh);
                }
            }
        }
    }

#pragma unroll
    for (int nt = 0; nt < 4; nt++) {
        int ncol = n0 + wn * 32 + nt * 8 + t * 2;
        float2 bv;
        if (bias) bv = *(const float2*)(bias + ncol);
        else { bv.x = 0.f; bv.y = 0.f; }
#pragma unroll
        for (int mt = 0; mt < 2; mt++) {
            int mrow = m0 + wm * 32 + mt * 16 + g;
            float2 v0, v1;
            v0.x = acc[mt][nt][0] + bv.x; v0.y = acc[mt][nt][1] + bv.y;
            v1.x = acc[mt][nt][2] + bv.x; v1.y = acc[mt][nt][3] + bv.y;
            *(float2*)(C + (long long)mrow * N + ncol) = v0;
            *(float2*)(C + (long long)(mrow + 8) * N + ncol) = v1;
        }
    }
}

// ---------------- pack kernel: fp32 -> (bf16hi,bf16lo) pairs ----------------
__global__ void pack_mat(const float* __restrict__ src, uint2* __restrict__ dst, int n4) {
    int i = blockIdx.x * 256 + threadIdx.x;
    if (i < n4) {
        float4 f = ((const float4*)src)[i];
        uint2 a = pack2(f.x, f.y);
        uint2 b = pack2(f.z, f.w);
        uint4 o;
        o.x = a.x; o.y = a.y; o.z = b.x; o.w = b.y;
        ((uint4*)dst)[i] = o;
    }
}

// ---------------- heads + RMS + RoPE -> packed dst ----------------
__global__ void build_qk_rope(const float* __restrict__ enc_lin,
                              const float* __restrict__ img_lin,
                              const float* __restrict__ w_enc,
                              const float* __restrict__ w_img,
                              const float* __restrict__ cosb,
                              const float* __restrict__ sinb,
                              uint2* __restrict__ dstp)
{
    int s = blockIdx.x;
    int h = blockIdx.y;
    int d = threadIdx.x;
    const float* src;
    const float* w;
    if (s < TXT_) { src = enc_lin + (long long)s * HID_; w = w_enc; }
    else          { src = img_lin + (long long)(s - TXT_) * HID_; w = w_img; }
    float x = src[h * DHD + d];
    float ss = x * x;
#pragma unroll
    for (int o = 16; o; o >>= 1) ss += __shfl_xor_sync(0xffffffffu, ss, o);
    __shared__ float sred[4];
    int lane = d & 31, wid = d >> 5;
    if (lane == 0) sred[wid] = ss;
    __syncthreads();
    ss = sred[0] + sred[1] + sred[2] + sred[3];
    float r = rsqrtf(ss * (1.0f / DHD) + 1e-6f);
    float xn = x * r * w[d];
    float partner = __shfl_xor_sync(0xffffffffu, xn, 1);
    float rot = (d & 1) ? partner : -partner;
    long long si = (long long)s * DHD + d;
    float res = xn * cosb[si] + rot * sinb[si];
    float res1 = __shfl_down_sync(0xffffffffu, res, 1);
    if (!(d & 1))
        dstp[(((long long)h * SALL + s) * DHD + d) >> 1] = pack2(res, res1);
}

// rms -> packed dst[h][s][d-pairs]
__global__ void build_rms(const float* __restrict__ src, const float* __restrict__ w,
                          uint2* __restrict__ dstp, int Srows)
{
    int s = blockIdx.x;
    int h = blockIdx.y;
    int d = threadIdx.x;
    float x = src[(long long)s * HID_ + h * DHD + d];
    float ss = x * x;
#pragma unroll
    for (int o = 16; o; o >>= 1) ss += __shfl_xor_sync(0xffffffffu, ss, o);
    __shared__ float sred[4];
    int lane = d & 31, wid = d >> 5;
    if (lane == 0) sred[wid] = ss;
    __syncthreads();
    ss = sred[0] + sred[1] + sred[2] + sred[3];
    float r = rsqrtf(ss * (1.0f / DHD) + 1e-6f);
    float res = x * r * w[d];
    float res1 = __shfl_down_sync(0xffffffffu, res, 1);
    if (!(d & 1))
        dstp[(((long long)h * Srows + s) * DHD + d) >> 1] = pack2(res, res1);
}

// transpose to packed dst[h][d][s-pairs]. block (32,8), grid (S/32, DHD/32, HN)
__global__ void transpose_heads_p(const float* __restrict__ enc, const float* __restrict__ img,
                                  int ntxt, uint2* __restrict__ dst, int Srows)
{
    __shared__ float tbuf[32][33];
    int s0 = blockIdx.x * 32, d0 = blockIdx.y * 32, h = blockIdx.z;
    int tx = threadIdx.x, ty = threadIdx.y;
#pragma unroll
    for (int j = 0; j < 4; j++) {
        int s = s0 + ty + j * 8;
        const float* src = (s < ntxt) ? enc + (long long)s * HID_
                                      : img + (long long)(s - ntxt) * HID_;
        tbuf[ty + j * 8][tx] = src[h * DHD + d0 + tx];
    }
    __syncthreads();
    int Sp = Srows >> 1;
    if (tx < 16) {
#pragma unroll
        for (int j = 0; j < 4; j++) {
            int dl = ty + j * 8;
            int d = d0 + dl;
            float a = tbuf[2 * tx][dl];
            float b = tbuf[2 * tx + 1][dl];
            dst[((long long)h * DHD + d) * Sp + (s0 >> 1) + tx] = pack2(a, b);
        }
    }
}

// ---------------- softmax: fp32 in -> packed probabilities out --------------
__global__ void softmax_p(const float* __restrict__ S, uint2* __restrict__ P,
                          int ncols, float scale)
{
    long long row = blockIdx.x;
    const float* src = S + row * (long long)ncols;
    uint2* dst = P + row * (long long)(ncols >> 1);
    int tid = threadIdx.x;
    int np = ncols >> 1;
    float2 lv[3];
    int cnt = 0;
    float mx = -INFINITY;
    for (int j = tid; j < np; j += 256) {
        float2 v = ((const float2*)src)[j];
        v.x *= scale; v.y *= scale;
        lv[cnt++] = v;
        mx = fmaxf(mx, fmaxf(v.x, v.y));
    }
    __shared__ float sred[8];
    int lane = tid & 31, wid = tid >> 5;
#pragma unroll
    for (int o = 16; o; o >>= 1) mx = fmaxf(mx, __shfl_xor_sync(0xffffffffu, mx, o));
    if (lane == 0) sred[wid] = mx;
    __syncthreads();
    mx = sred[0];
#pragma unroll
    for (int i = 1; i < 8; i++) mx = fmaxf(mx, sred[i]);
    __syncthreads();
    float sum = 0.f;
    for (int c = 0; c < cnt; c++) {
        lv[c].x = expf(lv[c].x - mx);
        lv[c].y = expf(lv[c].y - mx);
        sum += lv[c].x + lv[c].y;
    }
#pragma unroll
    for (int o = 16; o; o >>= 1) sum += __shfl_xor_sync(0xffffffffu, sum, o);
    if (lane == 0) sred[wid] = sum;
    __syncthreads();
    sum = sred[0];
#pragma unroll
    for (int i = 1; i < 8; i++) sum += sred[i];
    float inv = 1.0f / sum;
    cnt = 0;
    for (int j = tid; j < np; j += 256) {
        dst[j] = pack2(lv[cnt].x * inv, lv[cnt].y * inv);
        cnt++;
    }
}

// ---------------- merge + bbox mask -> packed ----------------
__global__ void merge_img_p(const float* __restrict__ O, const float* __restrict__ ipO,
                            uint2* __restrict__ dstp)
{
    int l = blockIdx.x, h = blockIdx.y, d = threadIdx.x;
    int row = l >> 5, col = l & 31;
    float m = (row >= 8 && row < 24 && col >= 8 && col < 24) ? 1.0f : 0.0f;
    float res = O[((long long)h * SALL + TXT_ + l) * DHD + d] +
                m * ipO[((long long)h * IMG_ + l) * DHD + d];
    float res1 = __shfl_down_sync(0xffffffffu, res, 1);
    if (!(d & 1))
        dstp[((long long)l * HID_ + h * DHD + d) >> 1] = pack2(res, res1);
}

__global__ void merge_enc_p(const float* __restrict__ O, uint2* __restrict__ dstp)
{
    int s = blockIdx.x, h = blockIdx.y, d = threadIdx.x;
    float res = O[((long long)h * SALL + s) * DHD + d];
    float res1 = __shfl_down_sync(0xffffffffu, res, 1);
    if (!(d & 1))
        dstp[((long long)s * HID_ + h * DHD + d) >> 1] = pack2(res, res1);
}

// ---------------- launch ----------------
extern "C" void kernel_launch(void* const* d_in, const int* in_sizes, int n_in,
                              void* d_out, int out_size)
{
    const float* hidden   = (const float*)d_in[0];
    const float* enc_hs   = (const float*)d_in[1];
    const float* ip_hs    = (const float*)d_in[2];
    const float* rope_cos = (const float*)d_in[3];
    const float* rope_sin = (const float*)d_in[4];
    const float* Wq  = (const float*)d_in[5];
    const float* bq  = (const float*)d_in[6];
    const float* Wk  = (const float*)d_in[7];
    const float* bk  = (const float*)d_in[8];
    const float* Wv  = (const float*)d_in[9];
    const float* bv  = (const float*)d_in[10];
    const float* norm_q_w = (const float*)d_in[11];
    const float* norm_k_w = (const float*)d_in[12];
    const float* Wq_add = (const float*)d_in[13];
    const float* bq_add = (const float*)d_in[14];
    const float* Wk_add = (const float*)d_in[15];
    const float* bk_add = (const float*)d_in[16];
    const float* Wv_add = (const float*)d_in[17];
    const float* bv_add = (const float*)d_in[18];
    const float* norm_added_q_w = (const float*)d_in[19];
    const float* norm_added_k_w = (const float*)d_in[20];
    const float* W_out = (const float*)d_in[21];
    const float* b_out = (const float*)d_in[22];
    const float* W_add_out = (const float*)d_in[23];
    const float* b_add_out = (const float*)d_in[24];
    const float* W_k_ip = (const float*)d_in[25];
    const float* b_k_ip = (const float*)d_in[26];
    const float* W_v_ip = (const float*)d_in[27];
    const float* b_v_ip = (const float*)d_in[28];
    const float* norm_ip_q_w = (const float*)d_in[29];
    const float* norm_ip_k_w = (const float*)d_in[30];

    float* out_img = (float*)d_out;
    float* out_enc = out_img + (size_t)IMG_ * HID_;

    float *q, *k, *v, *eq, *ek, *ev, *ipk, *ipv, *Sb, *Sip, *O, *ipO;
    uint2 *hp, *ep, *ipp, *Wqp, *Wkp, *Wvp, *Wqap, *Wkap, *Wvap, *Wop, *Waop, *Wkipp, *Wvipp;
    uint2 *qfp, *kfp, *vtp, *ipqp, *ipkhp, *ipvtp, *Pp, *Sipp, *imgp, *encp;
    cudaGetSymbolAddress((void**)&q, g_q);
    cudaGetSymbolAddress((void**)&k, g_k);
    cudaGetSymbolAddress((void**)&v, g_v);
    cudaGetSymbolAddress((void**)&eq, g_eq);
    cudaGetSymbolAddress((void**)&ek, g_ek);
    cudaGetSymbolAddress((void**)&ev, g_ev);
    cudaGetSymbolAddress((void**)&ipk, g_ipk);
    cudaGetSymbolAddress((void**)&ipv, g_ipv);
    cudaGetSymbolAddress((void**)&Sb, g_S);
    cudaGetSymbolAddress((void**)&Sip, g_Sip);
    cudaGetSymbolAddress((void**)&O, g_O);
    cudaGetSymbolAddress((void**)&ipO, g_ipO);
    cudaGetSymbolAddress((void**)&hp, g_hp);
    cudaGetSymbolAddress((void**)&ep, g_ep);
    cudaGetSymbolAddress((void**)&ipp, g_ipp);
    cudaGetSymbolAddress((void**)&Wqp, g_Wq_p);
    cudaGetSymbolAddress((void**)&Wkp, g_Wk_p);
    cudaGetSymbolAddress((void**)&Wvp, g_Wv_p);
    cudaGetSymbolAddress((void**)&Wqap, g_Wqa_p);
    cudaGetSymbolAddress((void**)&Wkap, g_Wka_p);
    cudaGetSymbolAddress((void**)&Wvap, g_Wva_p);
    cudaGetSymbolAddress((void**)&Wop, g_Wo_p);
    cudaGetSymbolAddress((void**)&Waop, g_Wao_p);
    cudaGetSymbolAddress((void**)&Wkipp, g_Wkip_p);
    cudaGetSymbolAddress((void**)&Wvipp, g_Wvip_p);
    cudaGetSymbolAddress((void**)&qfp, g_qfp);
    cudaGetSymbolAddress((void**)&kfp, g_kfp);
    cudaGetSymbolAddress((void**)&vtp, g_vtp);
    cudaGetSymbolAddress((void**)&ipqp, g_ipqp);
    cudaGetSymbolAddress((void**)&ipkhp, g_ipkhp);
    cudaGetSymbolAddress((void**)&ipvtp, g_ipvtp);
    cudaGetSymbolAddress((void**)&Pp, g_Pp);
    cudaGetSymbolAddress((void**)&Sipp, g_Sipp);
    cudaGetSymbolAddress((void**)&imgp, g_imgp);
    cudaGetSymbolAddress((void**)&encp, g_encp);

    cudaFuncSetAttribute(gemm_tc, cudaFuncAttributeMaxDynamicSharedMemorySize, GSM);

    const float scale = 0.08838834764831845f; // 1/sqrt(128)

    // --- pack inputs & weights ---
    const int WW4 = HID_ * HID_ / 4, WIP4 = HID_ * IPD_ / 4;
    pack_mat<<<(IMG_ * HID_ / 4 + 255) / 256, 256>>>(hidden, hp, IMG_ * HID_ / 4);
    pack_mat<<<(TXT_ * HID_ / 4 + 255) / 256, 256>>>(enc_hs, ep, TXT_ * HID_ / 4);
    pack_mat<<<(IPL_ * IPD_ / 4 + 255) / 256, 256>>>(ip_hs, ipp, IPL_ * IPD_ / 4);
    pack_mat<<<(WW4 + 255) / 256, 256>>>(Wq, Wqp, WW4);
    pack_mat<<<(WW4 + 255) / 256, 256>>>(Wk, Wkp, WW4);
    pack_mat<<<(WW4 + 255) / 256, 256>>>(Wv, Wvp, WW4);
    pack_mat<<<(WW4 + 255) / 256, 256>>>(Wq_add, Wqap, WW4);
    pack_mat<<<(WW4 + 255) / 256, 256>>>(Wk_add, Wkap, WW4);
    pack_mat<<<(WW4 + 255) / 256, 256>>>(Wv_add, Wvap, WW4);
    pack_mat<<<(WW4 + 255) / 256, 256>>>(W_out, Wop, WW4);
    pack_mat<<<(WW4 + 255) / 256, 256>>>(W_add_out, Waop, WW4);
    pack_mat<<<(WIP4 + 255) / 256, 256>>>(W_k_ip, Wkipp, WIP4);
    pack_mat<<<(WIP4 + 255) / 256, 256>>>(W_v_ip, Wvipp, WIP4);

    const int HIDp = HID_ / 2, IPDp = IPD_ / 2, DHp = DHD / 2, SAp = SALL / 2, IPLp = IPL_ / 2;

    // --- projections ---
    gemm_tc<<<dim3(HID_ / 64, IMG_ / 128), 256, GSM>>>(hp, Wqp, bq, q, IMG_, HID_, HIDp, 0, 0, 0);
    gemm_tc<<<dim3(HID_ / 64, IMG_ / 128), 256, GSM>>>(hp, Wkp, bk, k, IMG_, HID_, HIDp, 0, 0, 0);
    gemm_tc<<<dim3(HID_ / 64, IMG_ / 128), 256, GSM>>>(hp, Wvp, bv, v, IMG_, HID_, HIDp, 0, 0, 0);
    gemm_tc<<<dim3(HID_ / 64, TXT_ / 128), 256, GSM>>>(ep, Wqap, bq_add, eq, TXT_, HID_, HIDp, 0, 0, 0);
    gemm_tc<<<dim3(HID_ / 64, TXT_ / 128), 256, GSM>>>(ep, Wkap, bk_add, ek, TXT_, HID_, HIDp, 0, 0, 0);
    gemm_tc<<<dim3(HID_ / 64, TXT_ / 128), 256, GSM>>>(ep, Wvap, bv_add, ev, TXT_, HID_, HIDp, 0, 0, 0);
    gemm_tc<<<dim3(HID_ / 64, IPL_ / 128), 256, GSM>>>(ipp, Wkipp, b_k_ip, ipk, IPL_, HID_, IPDp, 0, 0, 0);
    gemm_tc<<<dim3(HID_ / 64, IPL_ / 128), 256, GSM>>>(ipp, Wvipp, b_v_ip, ipv, IPL_, HID_, IPDp, 0, 0, 0);

    // --- heads / rms / rope / transposes (write packed) ---
    build_qk_rope<<<dim3(SALL, HN), 128>>>(eq, q, norm_added_q_w, norm_q_w, rope_cos, rope_sin, qfp);
    build_qk_rope<<<dim3(SALL, HN), 128>>>(ek, k, norm_added_k_w, norm_k_w, rope_cos, rope_sin, kfp);
    transpose_heads_p<<<dim3(SALL / 32, DHD / 32, HN), dim3(32, 8)>>>(ev, v, TXT_, vtp, SALL);
    build_rms<<<dim3(IMG_, HN), 128>>>(q, norm_ip_q_w, ipqp, IMG_);
    build_rms<<<dim3(IPL_, HN), 128>>>(ipk, norm_ip_k_w, ipkhp, IPL_);
    transpose_heads_p<<<dim3(IPL_ / 32, DHD / 32, HN), dim3(32, 8)>>>(ipv, ipv, IPL_, ipvtp, IPL_);

    // --- main attention ---
    gemm_tc<<<dim3(SALL / 64, SALL / 128, HN), 256, GSM>>>(
        qfp, kfp, nullptr, Sb, SALL, SALL, DHp,
        (long long)SALL * DHp, (long long)SALL * DHp, (long long)SALL * SALL);
    softmax_p<<<HN * SALL, 256>>>(Sb, Pp, SALL, scale);
    gemm_tc<<<dim3(DHD / 64, SALL / 128, HN), 256, GSM>>>(
        Pp, vtp, nullptr, O, SALL, DHD, SAp,
        (long long)SALL * SAp, (long long)DHD * SAp, (long long)SALL * DHD);

    // --- ip attention ---
    gemm_tc<<<dim3(IPL_ / 64, IMG_ / 128, HN), 256, GSM>>>(
        ipqp, ipkhp, nullptr, Sip, IMG_, IPL_, DHp,
        (long long)IMG_ * DHp, (long long)IPL_ * DHp, (long long)IMG_ * IPL_);
    softmax_p<<<HN * IMG_, 256>>>(Sip, Sipp, IPL_, scale);
    gemm_tc<<<dim3(DHD / 64, IMG_ / 128, HN), 256, GSM>>>(
        Sipp, ipvtp, nullptr, ipO, IMG_, DHD, IPLp,
        (long long)IMG_ * IPLp, (long long)DHD * IPLp, (long long)IMG_ * DHD);

    // --- merge + output projections ---
    merge_img_p<<<dim3(IMG_, HN), 128>>>(O, ipO, imgp);
    merge_enc_p<<<dim3(TXT_, HN), 128>>>(O, encp);
    gemm_tc<<<dim3(HID_ / 64, IMG_ / 128), 256, GSM>>>(imgp, Wop, b_out, out_img, IMG_, HID_, HIDp, 0, 0, 0);
    gemm_tc<<<dim3(HID_ / 64, TXT_ / 128), 256, GSM>>>(encp, Waop, b_add_out, out_enc, TXT_, HID_, HIDp, 0, 0, 0);
}

// round 7
// speedup vs baseline: 1.4469x; 1.0956x over previous
#include <cuda_runtime.h>
#include <cuda_bf16.h>
#include <math.h>
#include <stdint.h>

#define HN   24
#define DHD  128
#define TXT_ 512
#define IMG_ 1024
#define SALL 1536
#define HID_ 3072
#define IPD_ 1152
#define IPL_ 128
#define N3   (3 * HID_)      // 9216
#define N2   (2 * HID_)      // 6144

// ---------------- static scratch (allocation-free) ----------------
__device__ float g_qkv[IMG_ * N3];       // q|k|v per row
__device__ float g_eqkv[TXT_ * N3];      // eq|ek|ev per row
__device__ float g_ipkv[IPL_ * N2];      // ipk|ipv per row
__device__ float g_S[HN * SALL * SALL];
__device__ float g_Sip[HN * IMG_ * IPL_];
__device__ float g_O[HN * SALL * DHD];
__device__ float g_ipO[HN * IMG_ * DHD];
__device__ float g_bqkv[N3];
__device__ float g_beqkv[N3];
__device__ float g_bip[N2];
// packed (bf16 hi/lo pairs) GEMM operands
__device__ uint2 g_hp[IMG_ * HID_ / 2];
__device__ uint2 g_ep[TXT_ * HID_ / 2];
__device__ uint2 g_ipp[IPL_ * IPD_ / 2];
__device__ uint2 g_Wqkv_p[N3 * HID_ / 2];
__device__ uint2 g_Weqkv_p[N3 * HID_ / 2];
__device__ uint2 g_Wip_p[N2 * IPD_ / 2];
__device__ uint2 g_Wo_p[HID_ * HID_ / 2];
__device__ uint2 g_Wao_p[HID_ * HID_ / 2];
__device__ uint2 g_qfp[HN * SALL * DHD / 2];
__device__ uint2 g_kfp[HN * SALL * DHD / 2];
__device__ uint2 g_vtp[HN * DHD * SALL / 2];
__device__ uint2 g_ipqp[HN * IMG_ * DHD / 2];
__device__ uint2 g_ipkhp[HN * IPL_ * DHD / 2];
__device__ uint2 g_ipvtp[HN * DHD * IPL_ / 2];
__device__ uint2 g_Pp[HN * SALL * SALL / 2];
__device__ uint2 g_Sipp[HN * IMG_ * IPL_ / 2];
__device__ uint2 g_imgp[IMG_ * HID_ / 2];
__device__ uint2 g_encp[TXT_ * HID_ / 2];

// ---------------- bf16 hi/lo split helpers ----------------
__device__ __forceinline__ uint2 pack2(float f0, float f1) {
    __nv_bfloat16 h0 = __float2bfloat16(f0);
    __nv_bfloat16 h1 = __float2bfloat16(f1);
    __nv_bfloat16 l0 = __float2bfloat16(f0 - __bfloat162float(h0));
    __nv_bfloat16 l1 = __float2bfloat16(f1 - __bfloat162float(h1));
    uint2 u;
    u.x = (unsigned)__bfloat16_as_ushort(h0) | ((unsigned)__bfloat16_as_ushort(h1) << 16);
    u.y = (unsigned)__bfloat16_as_ushort(l0) | ((unsigned)__bfloat16_as_ushort(l1) << 16);
    return u;
}

__device__ __forceinline__ void mma_bf16(float* d, const unsigned* a, const unsigned* b) {
    asm volatile(
        "mma.sync.aligned.m16n8k16.row.col.f32.bf16.bf16.f32 "
        "{%0,%1,%2,%3}, {%4,%5,%6,%7}, {%8,%9}, {%0,%1,%2,%3};"
        : "+f"(d[0]), "+f"(d[1]), "+f"(d[2]), "+f"(d[3])
        : "r"(a[0]), "r"(a[1]), "r"(a[2]), "r"(a[3]), "r"(b[0]), "r"(b[1]));
}

// smem pair index with xor swizzle: row r, pair e (0..15)
__device__ __forceinline__ int sidx(int r, int e) {
    return r * 16 + (e ^ ((r & 3) << 2));
}

__device__ __forceinline__ void cpa16(uint32_t dst, const void* src) {
    asm volatile("cp.async.cg.shared.global [%0], [%1], 16;" :: "r"(dst), "l"(src));
}
__device__ __forceinline__ void cp_commit() {
    asm volatile("cp.async.commit_group;" ::: "memory");
}
template <int NN>
__device__ __forceinline__ void cp_wait() {
    asm volatile("cp.async.wait_group %0;" :: "n"(NN) : "memory");
}

// ---------------- bf16x3 GEMM (NT, packed, cp.async 3-stage) ----------------
// C[M,N] = A[M,K] * B[N,K]^T + bias.  A,B packed uint2 (Kp = K/2).
// BM=128, BN=128, BK=32 (16 pairs), 256 threads, 8 warps (4x2), warp 32x64.
// Dynamic smem: 3 stages x (A 16KB + B 16KB) = 96 KB.
#define GST   3
#define STGB  32768
#define GSM   (GST * STGB)

__global__ __launch_bounds__(256, 2) void gemm_tc(
    const uint2* __restrict__ A, const uint2* __restrict__ B,
    const float* __restrict__ bias, float* __restrict__ C,
    int M, int N, int Kp,
    long long sA, long long sB, long long sC)
{
    A += (long long)blockIdx.z * sA;
    B += (long long)blockIdx.z * sB;
    C += (long long)blockIdx.z * sC;

    extern __shared__ __align__(16) char smem[];
    uint32_t sb = (uint32_t)__cvta_generic_to_shared(smem);

    int tid = threadIdx.x;
    int warp = tid >> 5, lane = tid & 31;
    int wm = warp >> 1, wn = warp & 1;
    int m0 = blockIdx.y * 128, n0 = blockIdx.x * 128;
    int g = lane >> 2, t = lane & 3;

    float acc[2][8][4];
#pragma unroll
    for (int mt = 0; mt < 2; mt++)
#pragma unroll
        for (int nt = 0; nt < 8; nt++)
#pragma unroll
            for (int i = 0; i < 4; i++) acc[mt][nt][i] = 0.f;

    int nkt = Kp >> 4;
    int lrow = tid >> 3;            // 0..31 (+32*it)
    int lq = (tid & 7) << 1;        // pair 0,2..14

#define LOAD_STAGE(kt, s)                                                              \
    {                                                                                  \
        int kb = (kt) << 4;                                                            \
        uint32_t ab = sb + (s) * STGB;                                                 \
        uint32_t bb = ab + 16384;                                                      \
        _Pragma("unroll")                                                              \
        for (int it = 0; it < 4; it++) {                                               \
            int row = lrow + it * 32;                                                  \
            cpa16(ab + sidx(row, lq) * 8, A + (long long)(m0 + row) * Kp + kb + lq);   \
        }                                                                              \
        _Pragma("unroll")                                                              \
        for (int it = 0; it < 4; it++) {                                               \
            int row = lrow + it * 32;                                                  \
            cpa16(bb + sidx(row, lq) * 8, B + (long long)(n0 + row) * Kp + kb + lq);   \
        }                                                                              \
    }

    LOAD_STAGE(0, 0);
    cp_commit();
    if (nkt > 1) { LOAD_STAGE(1, 1); }
    cp_commit();

    for (int kt = 0; kt < nkt; kt++) {
        cp_wait<1>();
        __syncthreads();
        if (kt + 2 < nkt) {
            int s = (kt + 2) % GST;
            LOAD_STAGE(kt + 2, s);
        }
        cp_commit();

        const uint2* Ap = (const uint2*)(smem + (kt % GST) * STGB);
        const uint2* Bp = (const uint2*)(smem + (kt % GST) * STGB + 16384);

#pragma unroll
        for (int kc = 0; kc < 2; kc++) {
            int e0 = kc * 8 + t;
            unsigned ah[2][4], al[2][4];
#pragma unroll
            for (int mt = 0; mt < 2; mt++) {
                int mr = wm * 32 + mt * 16 + g;
                uint2 u0 = Ap[sidx(mr, e0)];
                uint2 u1 = Ap[sidx(mr + 8, e0)];
                uint2 u2 = Ap[sidx(mr, e0 + 4)];
                uint2 u3 = Ap[sidx(mr + 8, e0 + 4)];
                ah[mt][0] = u0.x; al[mt][0] = u0.y;
                ah[mt][1] = u1.x; al[mt][1] = u1.y;
                ah[mt][2] = u2.x; al[mt][2] = u2.y;
                ah[mt][3] = u3.x; al[mt][3] = u3.y;
            }
#pragma unroll
            for (int nt = 0; nt < 8; nt++) {
                int nr = wn * 64 + nt * 8 + g;
                uint2 v0 = Bp[sidx(nr, e0)];
                uint2 v1 = Bp[sidx(nr, e0 + 4)];
                unsigned bh[2] = { v0.x, v1.x };
                unsigned bl[2] = { v0.y, v1.y };
#pragma unroll
                for (int mt = 0; mt < 2; mt++) {
                    mma_bf16(acc[mt][nt], ah[mt], bh);
                    mma_bf16(acc[mt][nt], ah[mt], bl);
                    mma_bf16(acc[mt][nt], al[mt], bh);
                }
            }
        }
    }

#pragma unroll
    for (int nt = 0; nt < 8; nt++) {
        int ncol = n0 + wn * 64 + nt * 8 + t * 2;
        float2 bv;
        if (bias) bv = *(const float2*)(bias + ncol);
        else { bv.x = 0.f; bv.y = 0.f; }
#pragma unroll
        for (int mt = 0; mt < 2; mt++) {
            int mrow = m0 + wm * 32 + mt * 16 + g;
            float2 v0, v1;
            v0.x = acc[mt][nt][0] + bv.x; v0.y = acc[mt][nt][1] + bv.y;
            v1.x = acc[mt][nt][2] + bv.x; v1.y = acc[mt][nt][3] + bv.y;
            *(float2*)(C + (long long)mrow * N + ncol) = v0;
            *(float2*)(C + (long long)(mrow + 8) * N + ncol) = v1;
        }
    }
}

// ---------------- pack kernel: fp32 -> (bf16hi,bf16lo) pairs ----------------
__global__ void pack_mat(const float* __restrict__ src, uint2* __restrict__ dst, int n4) {
    int i = blockIdx.x * 256 + threadIdx.x;
    if (i < n4) {
        float4 f = ((const float4*)src)[i];
        uint2 a = pack2(f.x, f.y);
        uint2 b = pack2(f.z, f.w);
        uint4 o;
        o.x = a.x; o.y = a.y; o.z = b.x; o.w = b.y;
        ((uint4*)dst)[i] = o;
    }
}

// ---------------- bias concat ----------------
__global__ void concat3(const float* __restrict__ a, const float* __restrict__ b,
                        const float* __restrict__ c, float* __restrict__ d, int n) {
    int i = blockIdx.x * 256 + threadIdx.x;
    if (i < n) d[i] = a[i];
    else if (i < 2 * n) d[i] = b[i - n];
    else if (i < 3 * n) d[i] = c[i - 2 * n];
}
__global__ void concat2(const float* __restrict__ a, const float* __restrict__ b,
                        float* __restrict__ d, int n) {
    int i = blockIdx.x * 256 + threadIdx.x;
    if (i < n) d[i] = a[i];
    else if (i < 2 * n) d[i] = b[i - n];
}

// ---------------- heads + RMS + RoPE -> packed dst ----------------
// enc_src/img_src point at the relevant column block (stride N3 rows)
__global__ void build_qk_rope(const float* __restrict__ enc_src,
                              const float* __restrict__ img_src,
                              const float* __restrict__ w_enc,
                              const float* __restrict__ w_img,
                              const float* __restrict__ cosb,
                              const float* __restrict__ sinb,
                              uint2* __restrict__ dstp)
{
    int s = blockIdx.x;
    int h = blockIdx.y;
    int d = threadIdx.x;
    const float* src;
    const float* w;
    if (s < TXT_) { src = enc_src + (long long)s * N3; w = w_enc; }
    else          { src = img_src + (long long)(s - TXT_) * N3; w = w_img; }
    float x = src[h * DHD + d];
    float ss = x * x;
#pragma unroll
    for (int o = 16; o; o >>= 1) ss += __shfl_xor_sync(0xffffffffu, ss, o);
    __shared__ float sred[4];
    int lane = d & 31, wid = d >> 5;
    if (lane == 0) sred[wid] = ss;
    __syncthreads();
    ss = sred[0] + sred[1] + sred[2] + sred[3];
    float r = rsqrtf(ss * (1.0f / DHD) + 1e-6f);
    float xn = x * r * w[d];
    float partner = __shfl_xor_sync(0xffffffffu, xn, 1);
    float rot = (d & 1) ? partner : -partner;
    long long si = (long long)s * DHD + d;
    float res = xn * cosb[si] + rot * sinb[si];
    float res1 = __shfl_down_sync(0xffffffffu, res, 1);
    if (!(d & 1))
        dstp[(((long long)h * SALL + s) * DHD + d) >> 1] = pack2(res, res1);
}

// rms -> packed dst[h][s][d-pairs], src row stride `stride`
__global__ void build_rms(const float* __restrict__ src, int stride,
                          const float* __restrict__ w,
                          uint2* __restrict__ dstp, int Srows)
{
    int s = blockIdx.x;
    int h = blockIdx.y;
    int d = threadIdx.x;
    float x = src[(long long)s * stride + h * DHD + d];
    float ss = x * x;
#pragma unroll
    for (int o = 16; o; o >>= 1) ss += __shfl_xor_sync(0xffffffffu, ss, o);
    __shared__ float sred[4];
    int lane = d & 31, wid = d >> 5;
    if (lane == 0) sred[wid] = ss;
    __syncthreads();
    ss = sred[0] + sred[1] + sred[2] + sred[3];
    float r = rsqrtf(ss * (1.0f / DHD) + 1e-6f);
    float res = x * r * w[d];
    float res1 = __shfl_down_sync(0xffffffffu, res, 1);
    if (!(d & 1))
        dstp[(((long long)h * Srows + s) * DHD + d) >> 1] = pack2(res, res1);
}

// transpose to packed dst[h][d][s-pairs]. block (32,8), grid (S/32, DHD/32, HN)
__global__ void transpose_heads_p(const float* __restrict__ enc, const float* __restrict__ img,
                                  int stride, int ntxt, uint2* __restrict__ dst, int Srows)
{
    __shared__ float tbuf[32][33];
    int s0 = blockIdx.x * 32, d0 = blockIdx.y * 32, h = blockIdx.z;
    int tx = threadIdx.x, ty = threadIdx.y;
#pragma unroll
    for (int j = 0; j < 4; j++) {
        int s = s0 + ty + j * 8;
        const float* src = (s < ntxt) ? enc + (long long)s * stride
                                      : img + (long long)(s - ntxt) * stride;
        tbuf[ty + j * 8][tx] = src[h * DHD + d0 + tx];
    }
    __syncthreads();
    int Sp = Srows >> 1;
    if (tx < 16) {
#pragma unroll
        for (int j = 0; j < 4; j++) {
            int dl = ty + j * 8;
            int d = d0 + dl;
            float a = tbuf[2 * tx][dl];
            float b = tbuf[2 * tx + 1][dl];
            dst[((long long)h * DHD + d) * Sp + (s0 >> 1) + tx] = pack2(a, b);
        }
    }
}

// ---------------- softmax: fp32 in -> packed probabilities out --------------
__global__ void softmax_p(const float* __restrict__ S, uint2* __restrict__ P,
                          int ncols, float scale)
{
    long long row = blockIdx.x;
    const float* src = S + row * (long long)ncols;
    uint2* dst = P + row * (long long)(ncols >> 1);
    int tid = threadIdx.x;
    int np = ncols >> 1;
    float2 lv[3];
    int cnt = 0;
    float mx = -INFINITY;
    for (int j = tid; j < np; j += 256) {
        float2 v = ((const float2*)src)[j];
        v.x *= scale; v.y *= scale;
        lv[cnt++] = v;
        mx = fmaxf(mx, fmaxf(v.x, v.y));
    }
    __shared__ float sred[8];
    int lane = tid & 31, wid = tid >> 5;
#pragma unroll
    for (int o = 16; o; o >>= 1) mx = fmaxf(mx, __shfl_xor_sync(0xffffffffu, mx, o));
    if (lane == 0) sred[wid] = mx;
    __syncthreads();
    mx = sred[0];
#pragma unroll
    for (int i = 1; i < 8; i++) mx = fmaxf(mx, sred[i]);
    __syncthreads();
    float sum = 0.f;
    for (int c = 0; c < cnt; c++) {
        lv[c].x = expf(lv[c].x - mx);
        lv[c].y = expf(lv[c].y - mx);
        sum += lv[c].x + lv[c].y;
    }
#pragma unroll
    for (int o = 16; o; o >>= 1) sum += __shfl_xor_sync(0xffffffffu, sum, o);
    if (lane == 0) sred[wid] = sum;
    __syncthreads();
    sum = sred[0];
#pragma unroll
    for (int i = 1; i < 8; i++) sum += sred[i];
    float inv = 1.0f / sum;
    cnt = 0;
    for (int j = tid; j < np; j += 256) {
        dst[j] = pack2(lv[cnt].x * inv, lv[cnt].y * inv);
        cnt++;
    }
}

// ---------------- merge + bbox mask -> packed ----------------
__global__ void merge_img_p(const float* __restrict__ O, const float* __restrict__ ipO,
                            uint2* __restrict__ dstp)
{
    int l = blockIdx.x, h = blockIdx.y, d = threadIdx.x;
    int row = l >> 5, col = l & 31;
    float m = (row >= 8 && row < 24 && col >= 8 && col < 24) ? 1.0f : 0.0f;
    float res = O[((long long)h * SALL + TXT_ + l) * DHD + d] +
                m * ipO[((long long)h * IMG_ + l) * DHD + d];
    float res1 = __shfl_down_sync(0xffffffffu, res, 1);
    if (!(d & 1))
        dstp[((long long)l * HID_ + h * DHD + d) >> 1] = pack2(res, res1);
}

__global__ void merge_enc_p(const float* __restrict__ O, uint2* __restrict__ dstp)
{
    int s = blockIdx.x, h = blockIdx.y, d = threadIdx.x;
    float res = O[((long long)h * SALL + s) * DHD + d];
    float res1 = __shfl_down_sync(0xffffffffu, res, 1);
    if (!(d & 1))
        dstp[((long long)s * HID_ + h * DHD + d) >> 1] = pack2(res, res1);
}

// ---------------- launch ----------------
extern "C" void kernel_launch(void* const* d_in, const int* in_sizes, int n_in,
                              void* d_out, int out_size)
{
    const float* hidden   = (const float*)d_in[0];
    const float* enc_hs   = (const float*)d_in[1];
    const float* ip_hs    = (const float*)d_in[2];
    const float* rope_cos = (const float*)d_in[3];
    const float* rope_sin = (const float*)d_in[4];
    const float* Wq  = (const float*)d_in[5];
    const float* bq  = (const float*)d_in[6];
    const float* Wk  = (const float*)d_in[7];
    const float* bk  = (const float*)d_in[8];
    const float* Wv  = (const float*)d_in[9];
    const float* bv  = (const float*)d_in[10];
    const float* norm_q_w = (const float*)d_in[11];
    const float* norm_k_w = (const float*)d_in[12];
    const float* Wq_add = (const float*)d_in[13];
    const float* bq_add = (const float*)d_in[14];
    const float* Wk_add = (const float*)d_in[15];
    const float* bk_add = (const float*)d_in[16];
    const float* Wv_add = (const float*)d_in[17];
    const float* bv_add = (const float*)d_in[18];
    const float* norm_added_q_w = (const float*)d_in[19];
    const float* norm_added_k_w = (const float*)d_in[20];
    const float* W_out = (const float*)d_in[21];
    const float* b_out = (const float*)d_in[22];
    const float* W_add_out = (const float*)d_in[23];
    const float* b_add_out = (const float*)d_in[24];
    const float* W_k_ip = (const float*)d_in[25];
    const float* b_k_ip = (const float*)d_in[26];
    const float* W_v_ip = (const float*)d_in[27];
    const float* b_v_ip = (const float*)d_in[28];
    const float* norm_ip_q_w = (const float*)d_in[29];
    const float* norm_ip_k_w = (const float*)d_in[30];

    float* out_img = (float*)d_out;
    float* out_enc = out_img + (size_t)IMG_ * HID_;

    float *qkv, *eqkv, *ipkv, *Sb, *Sip, *O, *ipO, *bqkv, *beqkv, *bip;
    uint2 *hp, *ep, *ipp, *Wqkvp, *Weqkvp, *Wipp, *Wop, *Waop;
    uint2 *qfp, *kfp, *vtp, *ipqp, *ipkhp, *ipvtp, *Pp, *Sipp, *imgp, *encp;
    cudaGetSymbolAddress((void**)&qkv, g_qkv);
    cudaGetSymbolAddress((void**)&eqkv, g_eqkv);
    cudaGetSymbolAddress((void**)&ipkv, g_ipkv);
    cudaGetSymbolAddress((void**)&Sb, g_S);
    cudaGetSymbolAddress((void**)&Sip, g_Sip);
    cudaGetSymbolAddress((void**)&O, g_O);
    cudaGetSymbolAddress((void**)&ipO, g_ipO);
    cudaGetSymbolAddress((void**)&bqkv, g_bqkv);
    cudaGetSymbolAddress((void**)&beqkv, g_beqkv);
    cudaGetSymbolAddress((void**)&bip, g_bip);
    cudaGetSymbolAddress((void**)&hp, g_hp);
    cudaGetSymbolAddress((void**)&ep, g_ep);
    cudaGetSymbolAddress((void**)&ipp, g_ipp);
    cudaGetSymbolAddress((void**)&Wqkvp, g_Wqkv_p);
    cudaGetSymbolAddress((void**)&Weqkvp, g_Weqkv_p);
    cudaGetSymbolAddress((void**)&Wipp, g_Wip_p);
    cudaGetSymbolAddress((void**)&Wop, g_Wo_p);
    cudaGetSymbolAddress((void**)&Waop, g_Wao_p);
    cudaGetSymbolAddress((void**)&qfp, g_qfp);
    cudaGetSymbolAddress((void**)&kfp, g_kfp);
    cudaGetSymbolAddress((void**)&vtp, g_vtp);
    cudaGetSymbolAddress((void**)&ipqp, g_ipqp);
    cudaGetSymbolAddress((void**)&ipkhp, g_ipkhp);
    cudaGetSymbolAddress((void**)&ipvtp, g_ipvtp);
    cudaGetSymbolAddress((void**)&Pp, g_Pp);
    cudaGetSymbolAddress((void**)&Sipp, g_Sipp);
    cudaGetSymbolAddress((void**)&imgp, g_imgp);
    cudaGetSymbolAddress((void**)&encp, g_encp);

    cudaFuncSetAttribute(gemm_tc, cudaFuncAttributeMaxDynamicSharedMemorySize, GSM);

    const float scale = 0.08838834764831845f; // 1/sqrt(128)
    const int WW4 = HID_ * HID_ / 4, WIP4 = HID_ * IPD_ / 4;
    const long long WWU = (long long)HID_ * HID_ / 2;      // uint2 per 3072x3072 block
    const long long WIPU = (long long)HID_ * IPD_ / 2;

    // --- pack inputs & weights (weights into fused N-blocks) ---
    pack_mat<<<(IMG_ * HID_ / 4 + 255) / 256, 256>>>(hidden, hp, IMG_ * HID_ / 4);
    pack_mat<<<(TXT_ * HID_ / 4 + 255) / 256, 256>>>(enc_hs, ep, TXT_ * HID_ / 4);
    pack_mat<<<(IPL_ * IPD_ / 4 + 255) / 256, 256>>>(ip_hs, ipp, IPL_ * IPD_ / 4);
    pack_mat<<<(WW4 + 255) / 256, 256>>>(Wq, Wqkvp, WW4);
    pack_mat<<<(WW4 + 255) / 256, 256>>>(Wk, Wqkvp + WWU, WW4);
    pack_mat<<<(WW4 + 255) / 256, 256>>>(Wv, Wqkvp + 2 * WWU, WW4);
    pack_mat<<<(WW4 + 255) / 256, 256>>>(Wq_add, Weqkvp, WW4);
    pack_mat<<<(WW4 + 255) / 256, 256>>>(Wk_add, Weqkvp + WWU, WW4);
    pack_mat<<<(WW4 + 255) / 256, 256>>>(Wv_add, Weqkvp + 2 * WWU, WW4);
    pack_mat<<<(WIP4 + 255) / 256, 256>>>(W_k_ip, Wipp, WIP4);
    pack_mat<<<(WIP4 + 255) / 256, 256>>>(W_v_ip, Wipp + WIPU, WIP4);
    pack_mat<<<(WW4 + 255) / 256, 256>>>(W_out, Wop, WW4);
    pack_mat<<<(WW4 + 255) / 256, 256>>>(W_add_out, Waop, WW4);
    concat3<<<(N3 + 255) / 256, 256>>>(bq, bk, bv, bqkv, HID_);
    concat3<<<(N3 + 255) / 256, 256>>>(bq_add, bk_add, bv_add, beqkv, HID_);
    concat2<<<(N2 + 255) / 256, 256>>>(b_k_ip, b_v_ip, bip, HID_);

    const int HIDp = HID_ / 2, IPDp = IPD_ / 2, DHp = DHD / 2, SAp = SALL / 2, IPLp = IPL_ / 2;

    // --- fused projections ---
    gemm_tc<<<dim3(N3 / 128, IMG_ / 128), 256, GSM>>>(hp, Wqkvp, bqkv, qkv, IMG_, N3, HIDp, 0, 0, 0);
    gemm_tc<<<dim3(N3 / 128, TXT_ / 128), 256, GSM>>>(ep, Weqkvp, beqkv, eqkv, TXT_, N3, HIDp, 0, 0, 0);
    gemm_tc<<<dim3(N2 / 128, IPL_ / 128), 256, GSM>>>(ipp, Wipp, bip, ipkv, IPL_, N2, IPDp, 0, 0, 0);

    // --- heads / rms / rope / transposes (write packed) ---
    // qkv layout: q at col 0, k at +3072, v at +6144; eqkv likewise; ipkv: k 0, v +3072
    build_qk_rope<<<dim3(SALL, HN), 128>>>(eqkv, qkv, norm_added_q_w, norm_q_w, rope_cos, rope_sin, qfp);
    build_qk_rope<<<dim3(SALL, HN), 128>>>(eqkv + HID_, qkv + HID_, norm_added_k_w, norm_k_w, rope_cos, rope_sin, kfp);
    transpose_heads_p<<<dim3(SALL / 32, DHD / 32, HN), dim3(32, 8)>>>(eqkv + 2 * HID_, qkv + 2 * HID_, N3, TXT_, vtp, SALL);
    build_rms<<<dim3(IMG_, HN), 128>>>(qkv, N3, norm_ip_q_w, ipqp, IMG_);
    build_rms<<<dim3(IPL_, HN), 128>>>(ipkv, N2, norm_ip_k_w, ipkhp, IPL_);
    transpose_heads_p<<<dim3(IPL_ / 32, DHD / 32, HN), dim3(32, 8)>>>(ipkv + HID_, ipkv + HID_, N2, IPL_, ipvtp, IPL_);

    // --- main attention ---
    gemm_tc<<<dim3(SALL / 128, SALL / 128, HN), 256, GSM>>>(
        qfp, kfp, nullptr, Sb, SALL, SALL, DHp,
        (long long)SALL * DHp, (long long)SALL * DHp, (long long)SALL * SALL);
    softmax_p<<<HN * SALL, 256>>>(Sb, Pp, SALL, scale);
    gemm_tc<<<dim3(DHD / 128, SALL / 128, HN), 256, GSM>>>(
        Pp, vtp, nullptr, O, SALL, DHD, SAp,
        (long long)SALL * SAp, (long long)DHD * SAp, (long long)SALL * DHD);

    // --- ip attention ---
    gemm_tc<<<dim3(IPL_ / 128, IMG_ / 128, HN), 256, GSM>>>(
        ipqp, ipkhp, nullptr, Sip, IMG_, IPL_, DHp,
        (long long)IMG_ * DHp, (long long)IPL_ * DHp, (long long)IMG_ * IPL_);
    softmax_p<<<HN * IMG_, 256>>>(Sip, Sipp, IPL_, scale);
    gemm_tc<<<dim3(DHD / 128, IMG_ / 128, HN), 256, GSM>>>(
        Sipp, ipvtp, nullptr, ipO, IMG_, DHD, IPLp,
        (long long)IMG_ * IPLp, (long long)DHD * IPLp, (long long)IMG_ * DHD);

    // --- merge + output projections ---
    merge_img_p<<<dim3(IMG_, HN), 128>>>(O, ipO, imgp);
    merge_enc_p<<<dim3(TXT_, HN), 128>>>(O, encp);
    gemm_tc<<<dim3(HID_ / 128, IMG_ / 128), 256, GSM>>>(imgp, Wop, b_out, out_img, IMG_, HID_, HIDp, 0, 0, 0);
    gemm_tc<<<dim3(HID_ / 128, TXT_ / 128), 256, GSM>>>(encp, Waop, b_add_out, out_enc, TXT_, HID_, HIDp, 0, 0, 0);
}

// round 9
// speedup vs baseline: 1.5607x; 1.0787x over previous
#include <cuda_runtime.h>
#include <cuda_bf16.h>
#include <math.h>
#include <stdint.h>

#define HN   24
#define DHD  128
#define TXT_ 512
#define IMG_ 1024
#define SALL 1536
#define HID_ 3072
#define IPD_ 1152
#define IPL_ 128
#define N3   (3 * HID_)
#define N2   (2 * HID_)

// plane sizes (elements per hi plane; lo plane at +plane)
#define PH    (IMG_ * HID_)
#define PE    (TXT_ * HID_)
#define PIP   (IPL_ * IPD_)
#define PW    (HID_ * HID_)
#define PW3   (N3 * HID_)
#define PW2   (N2 * IPD_)
#define PQF   (HN * SALL * DHD)
#define PVT   (HN * DHD * SALL)
#define PPR   (HN * SALL * SALL)
#define PSIP  (HN * IMG_ * IPL_)
#define PIPQ  (HN * IMG_ * DHD)
#define PIPK  (HN * IPL_ * DHD)
#define PIPVT (HN * DHD * IPL_)
#define PIMG  (IMG_ * HID_)
#define PENC  (TXT_ * HID_)

// ---------------- static scratch ----------------
__device__ float g_qkv[IMG_ * N3];
__device__ float g_eqkv[TXT_ * N3];
__device__ float g_ipkv[IPL_ * N2];
__device__ float g_S[HN * SALL * SALL];
__device__ float g_Sip[HN * IMG_ * IPL_];
__device__ float g_O[HN * SALL * DHD];
__device__ float g_ipO[HN * IMG_ * DHD];
__device__ float g_bqkv[N3];
__device__ float g_beqkv[N3];
__device__ float g_bip[N2];
// bf16 hi/lo plane pairs
__device__ __nv_bfloat16 g_hb[2 * PH];
__device__ __nv_bfloat16 g_eb[2 * PE];
__device__ __nv_bfloat16 g_ipb[2 * PIP];
__device__ __nv_bfloat16 g_Wqkv_b[2 * PW3];
__device__ __nv_bfloat16 g_Weqkv_b[2 * PW3];
__device__ __nv_bfloat16 g_Wip_b[2 * PW2];
__device__ __nv_bfloat16 g_Wo_b[2 * PW];
__device__ __nv_bfloat16 g_Wao_b[2 * PW];
__device__ __nv_bfloat16 g_qf_b[2 * PQF];
__device__ __nv_bfloat16 g_kf_b[2 * PQF];
__device__ __nv_bfloat16 g_vt_b[2 * PVT];
__device__ __nv_bfloat16 g_P_b[2 * PPR];
__device__ __nv_bfloat16 g_Sip_b[2 * PSIP];
__device__ __nv_bfloat16 g_ipq_b[2 * PIPQ];
__device__ __nv_bfloat16 g_ipk_b[2 * PIPK];
__device__ __nv_bfloat16 g_ipvt_b[2 * PIPVT];
__device__ __nv_bfloat16 g_img_b[2 * PIMG];
__device__ __nv_bfloat16 g_enc_b[2 * PENC];

// ---------------- helpers ----------------
__device__ __forceinline__ void split1(float x, __nv_bfloat16& h, __nv_bfloat16& l) {
    h = __float2bfloat16(x);
    l = __float2bfloat16(x - __bfloat162float(h));
}

__device__ __forceinline__ void mma_bf16(float* d, const unsigned* a, const unsigned* b) {
    asm volatile(
        "mma.sync.aligned.m16n8k16.row.col.f32.bf16.bf16.f32 "
        "{%0,%1,%2,%3}, {%4,%5,%6,%7}, {%8,%9}, {%0,%1,%2,%3};"
        : "+f"(d[0]), "+f"(d[1]), "+f"(d[2]), "+f"(d[3])
        : "r"(a[0]), "r"(a[1]), "r"(a[2]), "r"(a[3]), "r"(b[0]), "r"(b[1]));
}

__device__ __forceinline__ void ldsm4(uint32_t addr, unsigned* r) {
    asm volatile("ldmatrix.sync.aligned.m8n8.x4.shared.b16 {%0,%1,%2,%3}, [%4];"
        : "=r"(r[0]), "=r"(r[1]), "=r"(r[2]), "=r"(r[3]) : "r"(addr));
}

__device__ __forceinline__ void cpa16(uint32_t dst, const void* src) {
    asm volatile("cp.async.cg.shared.global [%0], [%1], 16;" :: "r"(dst), "l"(src));
}
__device__ __forceinline__ void cp_commit() {
    asm volatile("cp.async.commit_group;" ::: "memory");
}
template <int NN>
__device__ __forceinline__ void cp_wait() {
    asm volatile("cp.async.wait_group %0;" :: "n"(NN) : "memory");
}

// ---------------- bf16x3 GEMM (NT, hi/lo planes, ldmatrix, cp.async x3) ----
// C[M,N] = A[M,K]*B[N,K]^T + bias. A hi at A, lo at A+loA (elements). BK=32.
// BM=128, BN=128, 256 threads, 8 warps (4x2), warp 32x64.
// smem/stage: A 16KB + B 16KB (rows of 128B = hi 64B | lo 64B, 8-chunk xor swizzle)
#define GST   3
#define STGB  32768
#define GSM   (GST * STGB)

__global__ __launch_bounds__(256, 2) void gemm_tc(
    const __nv_bfloat16* __restrict__ A, long long loA,
    const __nv_bfloat16* __restrict__ B, long long loB,
    const float* __restrict__ bias, float* __restrict__ C,
    int M, int N, int K,
    long long sA, long long sB, long long sC)
{
    A += (long long)blockIdx.z * sA;
    B += (long long)blockIdx.z * sB;
    C += (long long)blockIdx.z * sC;

    extern __shared__ __align__(16) char smem[];
    uint32_t sb = (uint32_t)__cvta_generic_to_shared(smem);

    int tid = threadIdx.x;
    int warp = tid >> 5, lane = tid & 31;
    int wm = warp >> 1, wn = warp & 1;
    int m0 = blockIdx.y * 128, n0 = blockIdx.x * 128;
    int g = lane >> 2, t = lane & 3;
    int l7 = lane & 7, l8 = (lane >> 3) & 1, kh = lane >> 4;  // ldsm lane decomp

    float acc[2][8][4];
#pragma unroll
    for (int mt = 0; mt < 2; mt++)
#pragma unroll
        for (int nt = 0; nt < 8; nt++)
#pragma unroll
            for (int i = 0; i < 4; i++) acc[mt][nt][i] = 0.f;

    int nkt = K >> 5;

#define LOAD_STAGE(kt, s)                                                                \
    {                                                                                    \
        int kb = (kt) << 5;                                                              \
        uint32_t ab = sb + (s) * STGB;                                                   \
        uint32_t bb = ab + 16384;                                                        \
        _Pragma("unroll")                                                                \
        for (int it = 0; it < 4; it++) {                                                 \
            int idx = tid + it * 256;                                                    \
            int row = idx >> 3, c8 = idx & 7;                                            \
            int pl = c8 >> 2, c = c8 & 3;                                                \
            cpa16(ab + row * 128 + ((c8 ^ (row & 7)) << 4),                              \
                  A + (long long)pl * loA + (long long)(m0 + row) * K + kb + c * 8);     \
        }                                                                                \
        _Pragma("unroll")                                                                \
        for (int it = 0; it < 4; it++) {                                                 \
            int idx = tid + it * 256;                                                    \
            int row = idx >> 3, c8 = idx & 7;                                            \
            int pl = c8 >> 2, c = c8 & 3;                                                \
            cpa16(bb + row * 128 + ((c8 ^ (row & 7)) << 4),                              \
                  B + (long long)pl * loB + (long long)(n0 + row) * K + kb + c * 8);     \
        }                                                                                \
    }

    LOAD_STAGE(0, 0);
    cp_commit();
    if (nkt > 1) { LOAD_STAGE(1, 1); }
    cp_commit();

    for (int kt = 0; kt < nkt; kt++) {
        cp_wait<1>();
        __syncthreads();
        if (kt + 2 < nkt) {
            int s = (kt + 2) % GST;
            LOAD_STAGE(kt + 2, s);
        }
        cp_commit();

        uint32_t sA_ = sb + (kt % GST) * STGB;
        uint32_t sB_ = sA_ + 16384;

#pragma unroll
        for (int kc = 0; kc < 2; kc++) {
            int chunk = kc * 2 + kh;                  // 0..3
            unsigned ah[2][4], al[2][4];
#pragma unroll
            for (int mt = 0; mt < 2; mt++) {
                int row = wm * 32 + mt * 16 + l7 + l8 * 8;
                uint32_t base = sA_ + row * 128;
                ldsm4(base + ((chunk ^ (row & 7)) << 4), ah[mt]);
                ldsm4(base + (((chunk + 4) ^ (row & 7)) << 4), al[mt]);
            }
#pragma unroll
            for (int np = 0; np < 4; np++) {
                int row = wn * 64 + np * 16 + l7 + l8 * 8;
                uint32_t base = sB_ + row * 128;
                unsigned bh4[4], bl4[4];
                ldsm4(base + ((chunk ^ (row & 7)) << 4), bh4);
                ldsm4(base + (((chunk + 4) ^ (row & 7)) << 4), bl4);
#pragma unroll
                for (int sub = 0; sub < 2; sub++) {
                    int nt = np * 2 + sub;
                    // b0 = (n-group sub, k0-7) ; b1 = (n-group sub, k8-15)
                    unsigned bh[2] = { bh4[sub], bh4[sub + 2] };
                    unsigned bl[2] = { bl4[sub], bl4[sub + 2] };
#pragma unroll
                    for (int mt = 0; mt < 2; mt++) {
                        mma_bf16(acc[mt][nt], ah[mt], bh);
                        mma_bf16(acc[mt][nt], ah[mt], bl);
                        mma_bf16(acc[mt][nt], al[mt], bh);
                    }
                }
            }
        }
    }

#pragma unroll
    for (int nt = 0; nt < 8; nt++) {
        int ncol = n0 + wn * 64 + nt * 8 + t * 2;
        float2 bv;
        if (bias) bv = *(const float2*)(bias + ncol);
        else { bv.x = 0.f; bv.y = 0.f; }
#pragma unroll
        for (int mt = 0; mt < 2; mt++) {
            int mrow = m0 + wm * 32 + mt * 16 + g;
            float2 v0, v1;
            v0.x = acc[mt][nt][0] + bv.x; v0.y = acc[mt][nt][1] + bv.y;
            v1.x = acc[mt][nt][2] + bv.x; v1.y = acc[mt][nt][3] + bv.y;
            *(float2*)(C + (long long)mrow * N + ncol) = v0;
            *(float2*)(C + (long long)(mrow + 8) * N + ncol) = v1;
        }
    }
}

// ---------------- pack: fp32 -> bf16 hi/lo planes ----------------
__global__ void pack_split(const float* __restrict__ src, __nv_bfloat16* __restrict__ dst,
                           long long plane, int n4) {
    int i = blockIdx.x * 256 + threadIdx.x;
    if (i < n4) {
        float4 f = ((const float4*)src)[i];
        __nv_bfloat16 h0, h1, h2, h3, l0, l1, l2, l3;
        split1(f.x, h0, l0); split1(f.y, h1, l1);
        split1(f.z, h2, l2); split1(f.w, h3, l3);
        uint2 hi, lo;
        hi.x = (unsigned)__bfloat16_as_ushort(h0) | ((unsigned)__bfloat16_as_ushort(h1) << 16);
        hi.y = (unsigned)__bfloat16_as_ushort(h2) | ((unsigned)__bfloat16_as_ushort(h3) << 16);
        lo.x = (unsigned)__bfloat16_as_ushort(l0) | ((unsigned)__bfloat16_as_ushort(l1) << 16);
        lo.y = (unsigned)__bfloat16_as_ushort(l2) | ((unsigned)__bfloat16_as_ushort(l3) << 16);
        *(uint2*)(dst + 4ll * i) = hi;
        *(uint2*)(dst + plane + 4ll * i) = lo;
    }
}

// ---------------- bias concat ----------------
__global__ void concat3(const float* __restrict__ a, const float* __restrict__ b,
                        const float* __restrict__ c, float* __restrict__ d, int n) {
    int i = blockIdx.x * 256 + threadIdx.x;
    if (i < n) d[i] = a[i];
    else if (i < 2 * n) d[i] = b[i - n];
    else if (i < 3 * n) d[i] = c[i - 2 * n];
}
__global__ void concat2(const float* __restrict__ a, const float* __restrict__ b,
                        float* __restrict__ d, int n) {
    int i = blockIdx.x * 256 + threadIdx.x;
    if (i < n) d[i] = a[i];
    else if (i < 2 * n) d[i] = b[i - n];
}

// ---------------- heads + RMS + RoPE -> bf16 planes ----------------
__global__ void build_qk_rope(const float* __restrict__ enc_src,
                              const float* __restrict__ img_src,
                              const float* __restrict__ w_enc,
                              const float* __restrict__ w_img,
                              const float* __restrict__ cosb,
                              const float* __restrict__ sinb,
                              __nv_bfloat16* __restrict__ dst)
{
    int s = blockIdx.x, h = blockIdx.y, d = threadIdx.x;
    const float* src;
    const float* w;
    if (s < TXT_) { src = enc_src + (long long)s * N3; w = w_enc; }
    else          { src = img_src + (long long)(s - TXT_) * N3; w = w_img; }
    float x = src[h * DHD + d];
    float ss = x * x;
#pragma unroll
    for (int o = 16; o; o >>= 1) ss += __shfl_xor_sync(0xffffffffu, ss, o);
    __shared__ float sred[4];
    int lane = d & 31, wid = d >> 5;
    if (lane == 0) sred[wid] = ss;
    __syncthreads();
    ss = sred[0] + sred[1] + sred[2] + sred[3];
    float r = rsqrtf(ss * (1.0f / DHD) + 1e-6f);
    float xn = x * r * w[d];
    float partner = __shfl_xor_sync(0xffffffffu, xn, 1);
    float rot = (d & 1) ? partner : -partner;
    long long si = (long long)s * DHD + d;
    float res = xn * cosb[si] + rot * sinb[si];
    __nv_bfloat16 hh, ll;
    split1(res, hh, ll);
    long long idx = ((long long)h * SALL + s) * DHD + d;
    dst[idx] = hh;
    dst[idx + PQF] = ll;
}

// rms -> bf16 planes dst[h][s][d]
__global__ void build_rms(const float* __restrict__ src, int stride,
                          const float* __restrict__ w,
                          __nv_bfloat16* __restrict__ dst, int Srows, long long plane)
{
    int s = blockIdx.x, h = blockIdx.y, d = threadIdx.x;
    float x = src[(long long)s * stride + h * DHD + d];
    float ss = x * x;
#pragma unroll
    for (int o = 16; o; o >>= 1) ss += __shfl_xor_sync(0xffffffffu, ss, o);
    __shared__ float sred[4];
    int lane = d & 31, wid = d >> 5;
    if (lane == 0) sred[wid] = ss;
    __syncthreads();
    ss = sred[0] + sred[1] + sred[2] + sred[3];
    float r = rsqrtf(ss * (1.0f / DHD) + 1e-6f);
    float res = x * r * w[d];
    __nv_bfloat16 hh, ll;
    split1(res, hh, ll);
    long long idx = ((long long)h * Srows + s) * DHD + d;
    dst[idx] = hh;
    dst[idx + plane] = ll;
}

// transpose to bf16 planes dst[h][d][s]. block (32,8), grid (S/32, DHD/32, HN)
__global__ void transpose_heads_b(const float* __restrict__ enc, const float* __restrict__ img,
                                  int stride, int ntxt, __nv_bfloat16* __restrict__ dst,
                                  int Srows, long long plane)
{
    __shared__ float tbuf[32][33];
    int s0 = blockIdx.x * 32, d0 = blockIdx.y * 32, h = blockIdx.z;
    int tx = threadIdx.x, ty = threadIdx.y;
#pragma unroll
    for (int j = 0; j < 4; j++) {
        int s = s0 + ty + j * 8;
        const float* src = (s < ntxt) ? enc + (long long)s * stride
                                      : img + (long long)(s - ntxt) * stride;
        tbuf[ty + j * 8][tx] = src[h * DHD + d0 + tx];
    }
    __syncthreads();
#pragma unroll
    for (int j = 0; j < 4; j++) {
        int dl = ty + j * 8;
        int d = d0 + dl;
        float x = tbuf[tx][dl];
        __nv_bfloat16 hh, ll;
        split1(x, hh, ll);
        long long idx = ((long long)h * DHD + d) * Srows + s0 + tx;
        dst[idx] = hh;
        dst[idx + plane] = ll;
    }
}

// ---------------- softmax: fp32 in -> bf16 hi/lo planes out ----------------
__global__ void softmax_b(const float* __restrict__ S, __nv_bfloat16* __restrict__ P,
                          int ncols, float scale, long long plane)
{
    long long row = blockIdx.x;
    const float* src = S + row * (long long)ncols;
    __nv_bfloat16* dst = P + row * (long long)ncols;
    int tid = threadIdx.x;
    int np = ncols >> 1;
    float2 lv[3];
    int cnt = 0;
    float mx = -INFINITY;
    for (int j = tid; j < np; j += 256) {
        float2 v = ((const float2*)src)[j];
        v.x *= scale; v.y *= scale;
        lv[cnt++] = v;
        mx = fmaxf(mx, fmaxf(v.x, v.y));
    }
    __shared__ float sred[8];
    int lane = tid & 31, wid = tid >> 5;
#pragma unroll
    for (int o = 16; o; o >>= 1) mx = fmaxf(mx, __shfl_xor_sync(0xffffffffu, mx, o));
    if (lane == 0) sred[wid] = mx;
    __syncthreads();
    mx = sred[0];
#pragma unroll
    for (int i = 1; i < 8; i++) mx = fmaxf(mx, sred[i]);
    __syncthreads();
    float sum = 0.f;
    for (int c = 0; c < cnt; c++) {
        lv[c].x = expf(lv[c].x - mx);
        lv[c].y = expf(lv[c].y - mx);
        sum += lv[c].x + lv[c].y;
    }
#pragma unroll
    for (int o = 16; o; o >>= 1) sum += __shfl_xor_sync(0xffffffffu, sum, o);
    if (lane == 0) sred[wid] = sum;
    __syncthreads();
    sum = sred[0];
#pragma unroll
    for (int i = 1; i < 8; i++) sum += sred[i];
    float inv = 1.0f / sum;
    cnt = 0;
    for (int j = tid; j < np; j += 256) {
        float a = lv[cnt].x * inv, b = lv[cnt].y * inv;
        cnt++;
        __nv_bfloat16 ha, la, hb, lb;
        split1(a, ha, la); split1(b, hb, lb);
        unsigned hw = (unsigned)__bfloat16_as_ushort(ha) | ((unsigned)__bfloat16_as_ushort(hb) << 16);
        unsigned lw = (unsigned)__bfloat16_as_ushort(la) | ((unsigned)__bfloat16_as_ushort(lb) << 16);
        *(unsigned*)(dst + 2ll * j) = hw;
        *(unsigned*)(dst + plane + 2ll * j) = lw;
    }
}

// ---------------- merge + bbox mask -> bf16 planes ----------------
__global__ void merge_img_b(const float* __restrict__ O, const float* __restrict__ ipO,
                            __nv_bfloat16* __restrict__ dst)
{
    int l = blockIdx.x, h = blockIdx.y, d = threadIdx.x;
    int row = l >> 5, col = l & 31;
    float m = (row >= 8 && row < 24 && col >= 8 && col < 24) ? 1.0f : 0.0f;
    float res = O[((long long)h * SALL + TXT_ + l) * DHD + d] +
                m * ipO[((long long)h * IMG_ + l) * DHD + d];
    __nv_bfloat16 hh, ll;
    split1(res, hh, ll);
    long long idx = (long long)l * HID_ + h * DHD + d;
    dst[idx] = hh;
    dst[idx + PIMG] = ll;
}

__global__ void merge_enc_b(const float* __restrict__ O, __nv_bfloat16* __restrict__ dst)
{
    int s = blockIdx.x, h = blockIdx.y, d = threadIdx.x;
    float res = O[((long long)h * SALL + s) * DHD + d];
    __nv_bfloat16 hh, ll;
    split1(res, hh, ll);
    long long idx = (long long)s * HID_ + h * DHD + d;
    dst[idx] = hh;
    dst[idx + PENC] = ll;
}

// ---------------- launch ----------------
extern "C" void kernel_launch(void* const* d_in, const int* in_sizes, int n_in,
                              void* d_out, int out_size)
{
    const float* hidden   = (const float*)d_in[0];
    const float* enc_hs   = (const float*)d_in[1];
    const float* ip_hs    = (const float*)d_in[2];
    const float* rope_cos = (const float*)d_in[3];
    const float* rope_sin = (const float*)d_in[4];
    const float* Wq  = (const float*)d_in[5];
    const float* bq  = (const float*)d_in[6];
    const float* Wk  = (const float*)d_in[7];
    const float* bk  = (const float*)d_in[8];
    const float* Wv  = (const float*)d_in[9];
    const float* bv  = (const float*)d_in[10];
    const float* norm_q_w = (const float*)d_in[11];
    const float* norm_k_w = (const float*)d_in[12];
    const float* Wq_add = (const float*)d_in[13];
    const float* bq_add = (const float*)d_in[14];
    const float* Wk_add = (const float*)d_in[15];
    const float* bk_add = (const float*)d_in[16];
    const float* Wv_add = (const float*)d_in[17];
    const float* bv_add = (const float*)d_in[18];
    const float* norm_added_q_w = (const float*)d_in[19];
    const float* norm_added_k_w = (const float*)d_in[20];
    const float* W_out = (const float*)d_in[21];
    const float* b_out = (const float*)d_in[22];
    const float* W_add_out = (const float*)d_in[23];
    const float* b_add_out = (const float*)d_in[24];
    const float* W_k_ip = (const float*)d_in[25];
    const float* b_k_ip = (const float*)d_in[26];
    const float* W_v_ip = (const float*)d_in[27];
    const float* b_v_ip = (const float*)d_in[28];
    const float* norm_ip_q_w = (const float*)d_in[29];
    const float* norm_ip_k_w = (const float*)d_in[30];

    float* out_img = (float*)d_out;
    float* out_enc = out_img + (size_t)IMG_ * HID_;

    float *qkv, *eqkv, *ipkv, *Sb, *Sip, *O, *ipO, *bqkv, *beqkv, *bip;
    __nv_bfloat16 *hb, *eb, *ipb, *Wqkvb, *Weqkvb, *Wipb, *Wob, *Waob;
    __nv_bfloat16 *qfb, *kfb, *vtb, *Pb, *Sipb, *ipqb, *ipkb, *ipvtb, *imgb, *encb;
    cudaGetSymbolAddress((void**)&qkv, g_qkv);
    cudaGetSymbolAddress((void**)&eqkv, g_eqkv);
    cudaGetSymbolAddress((void**)&ipkv, g_ipkv);
    cudaGetSymbolAddress((void**)&Sb, g_S);
    cudaGetSymbolAddress((void**)&Sip, g_Sip);
    cudaGetSymbolAddress((void**)&O, g_O);
    cudaGetSymbolAddress((void**)&ipO, g_ipO);
    cudaGetSymbolAddress((void**)&bqkv, g_bqkv);
    cudaGetSymbolAddress((void**)&beqkv, g_beqkv);
    cudaGetSymbolAddress((void**)&bip, g_bip);
    cudaGetSymbolAddress((void**)&hb, g_hb);
    cudaGetSymbolAddress((void**)&eb, g_eb);
    cudaGetSymbolAddress((void**)&ipb, g_ipb);
    cudaGetSymbolAddress((void**)&Wqkvb, g_Wqkv_b);
    cudaGetSymbolAddress((void**)&Weqkvb, g_Weqkv_b);
    cudaGetSymbolAddress((void**)&Wipb, g_Wip_b);
    cudaGetSymbolAddress((void**)&Wob, g_Wo_b);
    cudaGetSymbolAddress((void**)&Waob, g_Wao_b);
    cudaGetSymbolAddress((void**)&qfb, g_qf_b);
    cudaGetSymbolAddress((void**)&kfb, g_kf_b);
    cudaGetSymbolAddress((void**)&vtb, g_vt_b);
    cudaGetSymbolAddress((void**)&Pb, g_P_b);
    cudaGetSymbolAddress((void**)&Sipb, g_Sip_b);
    cudaGetSymbolAddress((void**)&ipqb, g_ipq_b);
    cudaGetSymbolAddress((void**)&ipkb, g_ipk_b);
    cudaGetSymbolAddress((void**)&ipvtb, g_ipvt_b);
    cudaGetSymbolAddress((void**)&imgb, g_img_b);
    cudaGetSymbolAddress((void**)&encb, g_enc_b);

    cudaFuncSetAttribute(gemm_tc, cudaFuncAttributeMaxDynamicSharedMemorySize, GSM);

    const float scale = 0.08838834764831845f; // 1/sqrt(128)
    const int WW4 = PW / 4, WIP4 = (HID_ * IPD_) / 4;
    const long long WWE = (long long)PW;
    const long long WIPE = (long long)HID_ * IPD_;

    // --- pack inputs & weights into fused hi/lo planes ---
    pack_split<<<(PH / 4 + 255) / 256, 256>>>(hidden, hb, PH, PH / 4);
    pack_split<<<(PE / 4 + 255) / 256, 256>>>(enc_hs, eb, PE, PE / 4);
    pack_split<<<(PIP / 4 + 255) / 256, 256>>>(ip_hs, ipb, PIP, PIP / 4);
    pack_split<<<(WW4 + 255) / 256, 256>>>(Wq, Wqkvb, PW3, WW4);
    pack_split<<<(WW4 + 255) / 256, 256>>>(Wk, Wqkvb + WWE, PW3, WW4);
    pack_split<<<(WW4 + 255) / 256, 256>>>(Wv, Wqkvb + 2 * WWE, PW3, WW4);
    pack_split<<<(WW4 + 255) / 256, 256>>>(Wq_add, Weqkvb, PW3, WW4);
    pack_split<<<(WW4 + 255) / 256, 256>>>(Wk_add, Weqkvb + WWE, PW3, WW4);
    pack_split<<<(WW4 + 255) / 256, 256>>>(Wv_add, Weqkvb + 2 * WWE, PW3, WW4);
    pack_split<<<(WIP4 + 255) / 256, 256>>>(W_k_ip, Wipb, PW2, WIP4);
    pack_split<<<(WIP4 + 255) / 256, 256>>>(W_v_ip, Wipb + WIPE, PW2, WIP4);
    pack_split<<<(WW4 + 255) / 256, 256>>>(W_out, Wob, PW, WW4);
    pack_split<<<(WW4 + 255) / 256, 256>>>(W_add_out, Waob, PW, WW4);
    concat3<<<(N3 + 255) / 256, 256>>>(bq, bk, bv, bqkv, HID_);
    concat3<<<(N3 + 255) / 256, 256>>>(bq_add, bk_add, bv_add, beqkv, HID_);
    concat2<<<(N2 + 255) / 256, 256>>>(b_k_ip, b_v_ip, bip, HID_);

    // --- fused projections ---
    gemm_tc<<<dim3(N3 / 128, IMG_ / 128), 256, GSM>>>(hb, PH, Wqkvb, PW3, bqkv, qkv, IMG_, N3, HID_, 0, 0, 0);
    gemm_tc<<<dim3(N3 / 128, TXT_ / 128), 256, GSM>>>(eb, PE, Weqkvb, PW3, beqkv, eqkv, TXT_, N3, HID_, 0, 0, 0);
    gemm_tc<<<dim3(N2 / 128, IPL_ / 128), 256, GSM>>>(ipb, PIP, Wipb, PW2, bip, ipkv, IPL_, N2, IPD_, 0, 0, 0);

    // --- heads / rms / rope / transposes (write planes) ---
    build_qk_rope<<<dim3(SALL, HN), 128>>>(eqkv, qkv, norm_added_q_w, norm_q_w, rope_cos, rope_sin, qfb);
    build_qk_rope<<<dim3(SALL, HN), 128>>>(eqkv + HID_, qkv + HID_, norm_added_k_w, norm_k_w, rope_cos, rope_sin, kfb);
    transpose_heads_b<<<dim3(SALL / 32, DHD / 32, HN), dim3(32, 8)>>>(eqkv + 2 * HID_, qkv + 2 * HID_, N3, TXT_, vtb, SALL, PVT);
    build_rms<<<dim3(IMG_, HN), 128>>>(qkv, N3, norm_ip_q_w, ipqb, IMG_, PIPQ);
    build_rms<<<dim3(IPL_, HN), 128>>>(ipkv, N2, norm_ip_k_w, ipkb, IPL_, PIPK);
    transpose_heads_b<<<dim3(IPL_ / 32, DHD / 32, HN), dim3(32, 8)>>>(ipkv + HID_, ipkv + HID_, N2, IPL_, ipvtb, IPL_, PIPVT);

    // --- main attention ---
    gemm_tc<<<dim3(SALL / 128, SALL / 128, HN), 256, GSM>>>(
        qfb, PQF, kfb, PQF, nullptr, Sb, SALL, SALL, DHD,
        (long long)SALL * DHD, (long long)SALL * DHD, (long long)SALL * SALL);
    softmax_b<<<HN * SALL, 256>>>(Sb, Pb, SALL, scale, PPR);
    gemm_tc<<<dim3(DHD / 128, SALL / 128, HN), 256, GSM>>>(
        Pb, PPR, vtb, PVT, nullptr, O, SALL, DHD, SALL,
        (long long)SALL * SALL, (long long)DHD * SALL, (long long)SALL * DHD);

    // --- ip attention ---
    gemm_tc<<<dim3(IPL_ / 128, IMG_ / 128, HN), 256, GSM>>>(
        ipqb, PIPQ, ipkb, PIPK, nullptr, Sip, IMG_, IPL_, DHD,
        (long long)IMG_ * DHD, (long long)IPL_ * DHD, (long long)IMG_ * IPL_);
    softmax_b<<<HN * IMG_, 256>>>(Sip, Sipb, IPL_, scale, PSIP);
    gemm_tc<<<dim3(DHD / 128, IMG_ / 128, HN), 256, GSM>>>(
        Sipb, PSIP, ipvtb, PIPVT, nullptr, ipO, IMG_, DHD, IPL_,
        (long long)IMG_ * IPL_, (long long)DHD * IPL_, (long long)IMG_ * DHD);

    // --- merge + output projections ---
    merge_img_b<<<dim3(IMG_, HN), 128>>>(O, ipO, imgb);
    merge_enc_b<<<dim3(TXT_, HN), 128>>>(O, encb);
    gemm_tc<<<dim3(HID_ / 128, IMG_ / 128), 256, GSM>>>(imgb, PIMG, Wob, PW, b_out, out_img, IMG_, HID_, HID_, 0, 0, 0);
    gemm_tc<<<dim3(HID_ / 128, TXT_ / 128), 256, GSM>>>(encb, PENC, Waob, PW, b_add_out, out_enc, TXT_, HID_, HID_, 0, 0, 0);
}

// round 10
// speedup vs baseline: 2.1046x; 1.3485x over previous
#include <cuda_runtime.h>
#include <cuda_fp16.h>
#include <math.h>
#include <stdint.h>

#define HN   24
#define DHD  128
#define TXT_ 512
#define IMG_ 1024
#define SALL 1536
#define HID_ 3072
#define IPD_ 1152
#define IPL_ 128
#define N3   (3 * HID_)
#define N2   (2 * HID_)

// plane sizes (elements per hi plane; lo plane at +plane)
#define PH    (IMG_ * HID_)
#define PE    (TXT_ * HID_)
#define PIP   (IPL_ * IPD_)
#define PW    (HID_ * HID_)
#define PW3   (N3 * HID_)
#define PW2   (N2 * IPD_)
#define PQF   (HN * SALL * DHD)
#define PVT   (HN * DHD * SALL)
#define PPR   (HN * SALL * SALL)
#define PSIP  (HN * IMG_ * IPL_)
#define PIPQ  (HN * IMG_ * DHD)
#define PIPK  (HN * IPL_ * DHD)
#define PIPVT (HN * DHD * IPL_)
#define PIMG  (IMG_ * HID_)
#define PENC  (TXT_ * HID_)

// ---------------- static scratch ----------------
__device__ float g_qkv[IMG_ * N3];
__device__ float g_eqkv[TXT_ * N3];
__device__ float g_ipkv[IPL_ * N2];
__device__ float g_S[HN * SALL * SALL];
__device__ float g_Sip[HN * IMG_ * IPL_];
__device__ float g_O[HN * SALL * DHD];
__device__ float g_ipO[HN * IMG_ * DHD];
__device__ float g_bqkv[N3];
__device__ float g_beqkv[N3];
__device__ float g_bip[N2];
// fp16 hi/lo plane pairs
__device__ __half g_hb[2 * PH];
__device__ __half g_eb[2 * PE];
__device__ __half g_ipb[2 * PIP];
__device__ __half g_Wqkv_b[2 * PW3];
__device__ __half g_Weqkv_b[2 * PW3];
__device__ __half g_Wip_b[2 * PW2];
__device__ __half g_Wo_b[2 * PW];
__device__ __half g_Wao_b[2 * PW];
__device__ __half g_qf_b[2 * PQF];
__device__ __half g_kf_b[2 * PQF];
__device__ __half g_vt_b[2 * PVT];
__device__ __half g_P_b[2 * PPR];
__device__ __half g_Sip_b[2 * PSIP];
__device__ __half g_ipq_b[2 * PIPQ];
__device__ __half g_ipk_b[2 * PIPK];
__device__ __half g_ipvt_b[2 * PIPVT];
__device__ __half g_img_b[2 * PIMG];
__device__ __half g_enc_b[2 * PENC];

// ---------------- helpers ----------------
__device__ __forceinline__ void split1(float x, __half& h, __half& l) {
    h = __float2half_rn(x);
    l = __float2half_rn(x - __half2float(h));
}

__device__ __forceinline__ void mma_f16(float* d, const unsigned* a, const unsigned* b) {
    asm volatile(
        "mma.sync.aligned.m16n8k16.row.col.f32.f16.f16.f32 "
        "{%0,%1,%2,%3}, {%4,%5,%6,%7}, {%8,%9}, {%0,%1,%2,%3};"
        : "+f"(d[0]), "+f"(d[1]), "+f"(d[2]), "+f"(d[3])
        : "r"(a[0]), "r"(a[1]), "r"(a[2]), "r"(a[3]), "r"(b[0]), "r"(b[1]));
}

__device__ __forceinline__ void ldsm4(uint32_t addr, unsigned* r) {
    asm volatile("ldmatrix.sync.aligned.m8n8.x4.shared.b16 {%0,%1,%2,%3}, [%4];"
        : "=r"(r[0]), "=r"(r[1]), "=r"(r[2]), "=r"(r[3]) : "r"(addr));
}

__device__ __forceinline__ void cpa16(uint32_t dst, const void* src) {
    asm volatile("cp.async.cg.shared.global [%0], [%1], 16;" :: "r"(dst), "l"(src));
}
__device__ __forceinline__ void cp_commit() {
    asm volatile("cp.async.commit_group;" ::: "memory");
}
template <int NN>
__device__ __forceinline__ void cp_wait() {
    asm volatile("cp.async.wait_group %0;" :: "n"(NN) : "memory");
}

// ---------------- fp16 split GEMM (NT, hi/lo planes, ldmatrix, cp.async x3) --
// C[M,N] = A[M,K]*B[N,K]^T + bias. A hi at A, lo at A+loA (elements). BK=32.
// TERMS==3: ah*bh + ah*bl + al*bh.  TERMS==2: ah*bh + ah*bl (A-lo never touched).
// BM=128, BN=128, 256 threads, 8 warps (4x2), warp 32x64.
#define GST   3
#define STGB  32768
#define GSM   (GST * STGB)

template <int TERMS>
__global__ __launch_bounds__(256, 2) void gemm_tc(
    const __half* __restrict__ A, long long loA,
    const __half* __restrict__ B, long long loB,
    const float* __restrict__ bias, float* __restrict__ C,
    int M, int N, int K,
    long long sA, long long sB, long long sC)
{
    A += (long long)blockIdx.z * sA;
    B += (long long)blockIdx.z * sB;
    C += (long long)blockIdx.z * sC;

    extern __shared__ __align__(16) char smem[];
    uint32_t sb = (uint32_t)__cvta_generic_to_shared(smem);

    int tid = threadIdx.x;
    int warp = tid >> 5, lane = tid & 31;
    int wm = warp >> 1, wn = warp & 1;
    int m0 = blockIdx.y * 128, n0 = blockIdx.x * 128;
    int g = lane >> 2, t = lane & 3;
    int l7 = lane & 7, l8 = (lane >> 3) & 1, kh = lane >> 4;

    float acc[2][8][4];
#pragma unroll
    for (int mt = 0; mt < 2; mt++)
#pragma unroll
        for (int nt = 0; nt < 8; nt++)
#pragma unroll
            for (int i = 0; i < 4; i++) acc[mt][nt][i] = 0.f;

    int nkt = K >> 5;

#define LOAD_STAGE(kt, s)                                                                \
    {                                                                                    \
        int kb = (kt) << 5;                                                              \
        uint32_t ab = sb + (s) * STGB;                                                   \
        uint32_t bb = ab + 16384;                                                        \
        _Pragma("unroll")                                                                \
        for (int it = 0; it < 4; it++) {                                                 \
            int idx = tid + it * 256;                                                    \
            int row = idx >> 3, c8 = idx & 7;                                            \
            int pl = c8 >> 2, c = c8 & 3;                                                \
            if (TERMS == 3 || pl == 0)                                                   \
                cpa16(ab + row * 128 + ((c8 ^ (row & 7)) << 4),                          \
                      A + (long long)pl * loA + (long long)(m0 + row) * K + kb + c * 8); \
        }                                                                                \
        _Pragma("unroll")                                                                \
        for (int it = 0; it < 4; it++) {                                                 \
            int idx = tid + it * 256;                                                    \
            int row = idx >> 3, c8 = idx & 7;                                            \
            int pl = c8 >> 2, c = c8 & 3;                                                \
            cpa16(bb + row * 128 + ((c8 ^ (row & 7)) << 4),                              \
                  B + (long long)pl * loB + (long long)(n0 + row) * K + kb + c * 8);     \
        }                                                                                \
    }

    LOAD_STAGE(0, 0);
    cp_commit();
    if (nkt > 1) { LOAD_STAGE(1, 1); }
    cp_commit();

    for (int kt = 0; kt < nkt; kt++) {
        cp_wait<1>();
        __syncthreads();
        if (kt + 2 < nkt) {
            int s = (kt + 2) % GST;
            LOAD_STAGE(kt + 2, s);
        }
        cp_commit();

        uint32_t sA_ = sb + (kt % GST) * STGB;
        uint32_t sB_ = sA_ + 16384;

#pragma unroll
        for (int kc = 0; kc < 2; kc++) {
            int chunk = kc * 2 + kh;                  // 0..3
            unsigned ah[2][4], al[2][4];
#pragma unroll
            for (int mt = 0; mt < 2; mt++) {
                int row = wm * 32 + mt * 16 + l7 + l8 * 8;
                uint32_t base = sA_ + row * 128;
                ldsm4(base + ((chunk ^ (row & 7)) << 4), ah[mt]);
                if (TERMS == 3)
                    ldsm4(base + (((chunk + 4) ^ (row & 7)) << 4), al[mt]);
            }
#pragma unroll
            for (int np = 0; np < 4; np++) {
                int row = wn * 64 + np * 16 + l7 + l8 * 8;
                uint32_t base = sB_ + row * 128;
                unsigned bh4[4], bl4[4];
                ldsm4(base + ((chunk ^ (row & 7)) << 4), bh4);
                ldsm4(base + (((chunk + 4) ^ (row & 7)) << 4), bl4);
#pragma unroll
                for (int sub = 0; sub < 2; sub++) {
                    int nt = np * 2 + sub;
                    unsigned bh[2] = { bh4[sub], bh4[sub + 2] };
                    unsigned bl[2] = { bl4[sub], bl4[sub + 2] };
#pragma unroll
                    for (int mt = 0; mt < 2; mt++) {
                        mma_f16(acc[mt][nt], ah[mt], bh);
                        mma_f16(acc[mt][nt], ah[mt], bl);
                        if (TERMS == 3)
                            mma_f16(acc[mt][nt], al[mt], bh);
                    }
                }
            }
        }
    }

#pragma unroll
    for (int nt = 0; nt < 8; nt++) {
        int ncol = n0 + wn * 64 + nt * 8 + t * 2;
        float2 bv;
        if (bias) bv = *(const float2*)(bias + ncol);
        else { bv.x = 0.f; bv.y = 0.f; }
#pragma unroll
        for (int mt = 0; mt < 2; mt++) {
            int mrow = m0 + wm * 32 + mt * 16 + g;
            float2 v0, v1;
            v0.x = acc[mt][nt][0] + bv.x; v0.y = acc[mt][nt][1] + bv.y;
            v1.x = acc[mt][nt][2] + bv.x; v1.y = acc[mt][nt][3] + bv.y;
            *(float2*)(C + (long long)mrow * N + ncol) = v0;
            *(float2*)(C + (long long)(mrow + 8) * N + ncol) = v1;
        }
    }
}

// ---------------- pack: fp32 -> fp16 hi/lo planes ----------------
__global__ void pack_split(const float* __restrict__ src, __half* __restrict__ dst,
                           long long plane, int n4) {
    int i = blockIdx.x * 256 + threadIdx.x;
    if (i < n4) {
        float4 f = ((const float4*)src)[i];
        __half h0, h1, h2, h3, l0, l1, l2, l3;
        split1(f.x, h0, l0); split1(f.y, h1, l1);
        split1(f.z, h2, l2); split1(f.w, h3, l3);
        uint2 hi, lo;
        hi.x = (unsigned)__half_as_ushort(h0) | ((unsigned)__half_as_ushort(h1) << 16);
        hi.y = (unsigned)__half_as_ushort(h2) | ((unsigned)__half_as_ushort(h3) << 16);
        lo.x = (unsigned)__half_as_ushort(l0) | ((unsigned)__half_as_ushort(l1) << 16);
        lo.y = (unsigned)__half_as_ushort(l2) | ((unsigned)__half_as_ushort(l3) << 16);
        *(uint2*)(dst + 4ll * i) = hi;
        *(uint2*)(dst + plane + 4ll * i) = lo;
    }
}

// ---------------- bias concat ----------------
__global__ void concat3(const float* __restrict__ a, const float* __restrict__ b,
                        const float* __restrict__ c, float* __restrict__ d, int n) {
    int i = blockIdx.x * 256 + threadIdx.x;
    if (i < n) d[i] = a[i];
    else if (i < 2 * n) d[i] = b[i - n];
    else if (i < 3 * n) d[i] = c[i - 2 * n];
}
__global__ void concat2(const float* __restrict__ a, const float* __restrict__ b,
                        float* __restrict__ d, int n) {
    int i = blockIdx.x * 256 + threadIdx.x;
    if (i < n) d[i] = a[i];
    else if (i < 2 * n) d[i] = b[i - n];
}

// ---------------- heads + RMS + RoPE -> fp16 planes ----------------
__global__ void build_qk_rope(const float* __restrict__ enc_src,
                              const float* __restrict__ img_src,
                              const float* __restrict__ w_enc,
                              const float* __restrict__ w_img,
                              const float* __restrict__ cosb,
                              const float* __restrict__ sinb,
                              __half* __restrict__ dst)
{
    int s = blockIdx.x, h = blockIdx.y, d = threadIdx.x;
    const float* src;
    const float* w;
    if (s < TXT_) { src = enc_src + (long long)s * N3; w = w_enc; }
    else          { src = img_src + (long long)(s - TXT_) * N3; w = w_img; }
    float x = src[h * DHD + d];
    float ss = x * x;
#pragma unroll
    for (int o = 16; o; o >>= 1) ss += __shfl_xor_sync(0xffffffffu, ss, o);
    __shared__ float sred[4];
    int lane = d & 31, wid = d >> 5;
    if (lane == 0) sred[wid] = ss;
    __syncthreads();
    ss = sred[0] + sred[1] + sred[2] + sred[3];
    float r = rsqrtf(ss * (1.0f / DHD) + 1e-6f);
    float xn = x * r * w[d];
    float partner = __shfl_xor_sync(0xffffffffu, xn, 1);
    float rot = (d & 1) ? partner : -partner;
    long long si = (long long)s * DHD + d;
    float res = xn * cosb[si] + rot * sinb[si];
    __half hh, ll;
    split1(res, hh, ll);
    long long idx = ((long long)h * SALL + s) * DHD + d;
    dst[idx] = hh;
    dst[idx + PQF] = ll;
}

// rms -> fp16 planes dst[h][s][d]
__global__ void build_rms(const float* __restrict__ src, int stride,
                          const float* __restrict__ w,
                          __half* __restrict__ dst, int Srows, long long plane)
{
    int s = blockIdx.x, h = blockIdx.y, d = threadIdx.x;
    float x = src[(long long)s * stride + h * DHD + d];
    float ss = x * x;
#pragma unroll
    for (int o = 16; o; o >>= 1) ss += __shfl_xor_sync(0xffffffffu, ss, o);
    __shared__ float sred[4];
    int lane = d & 31, wid = d >> 5;
    if (lane == 0) sred[wid] = ss;
    __syncthreads();
    ss = sred[0] + sred[1] + sred[2] + sred[3];
    float r = rsqrtf(ss * (1.0f / DHD) + 1e-6f);
    float res = x * r * w[d];
    __half hh, ll;
    split1(res, hh, ll);
    long long idx = ((long long)h * Srows + s) * DHD + d;
    dst[idx] = hh;
    dst[idx + plane] = ll;
}

// transpose to fp16 planes dst[h][d][s]. block (32,8), grid (S/32, DHD/32, HN)
__global__ void transpose_heads_b(const float* __restrict__ enc, const float* __restrict__ img,
                                  int stride, int ntxt, __half* __restrict__ dst,
                                  int Srows, long long plane)
{
    __shared__ float tbuf[32][33];
    int s0 = blockIdx.x * 32, d0 = blockIdx.y * 32, h = blockIdx.z;
    int tx = threadIdx.x, ty = threadIdx.y;
#pragma unroll
    for (int j = 0; j < 4; j++) {
        int s = s0 + ty + j * 8;
        const float* src = (s < ntxt) ? enc + (long long)s * stride
                                      : img + (long long)(s - ntxt) * stride;
        tbuf[ty + j * 8][tx] = src[h * DHD + d0 + tx];
    }
    __syncthreads();
#pragma unroll
    for (int j = 0; j < 4; j++) {
        int dl = ty + j * 8;
        int d = d0 + dl;
        float x = tbuf[tx][dl];
        __half hh, ll;
        split1(x, hh, ll);
        long long idx = ((long long)h * DHD + d) * Srows + s0 + tx;
        dst[idx] = hh;
        dst[idx + plane] = ll;
    }
}

// ---------------- softmax: fp32 in -> fp16 hi/lo planes out ----------------
__global__ void softmax_b(const float* __restrict__ S, __half* __restrict__ P,
                          int ncols, float scale, long long plane)
{
    long long row = blockIdx.x;
    const float* src = S + row * (long long)ncols;
    __half* dst = P + row * (long long)ncols;
    int tid = threadIdx.x;
    int np = ncols >> 1;
    float2 lv[3];
    int cnt = 0;
    float mx = -INFINITY;
    for (int j = tid; j < np; j += 256) {
        float2 v = ((const float2*)src)[j];
        v.x *= scale; v.y *= scale;
        lv[cnt++] = v;
        mx = fmaxf(mx, fmaxf(v.x, v.y));
    }
    __shared__ float sred[8];
    int lane = tid & 31, wid = tid >> 5;
#pragma unroll
    for (int o = 16; o; o >>= 1) mx = fmaxf(mx, __shfl_xor_sync(0xffffffffu, mx, o));
    if (lane == 0) sred[wid] = mx;
    __syncthreads();
    mx = sred[0];
#pragma unroll
    for (int i = 1; i < 8; i++) mx = fmaxf(mx, sred[i]);
    __syncthreads();
    float sum = 0.f;
    for (int c = 0; c < cnt; c++) {
        lv[c].x = expf(lv[c].x - mx);
        lv[c].y = expf(lv[c].y - mx);
        sum += lv[c].x + lv[c].y;
    }
#pragma unroll
    for (int o = 16; o; o >>= 1) sum += __shfl_xor_sync(0xffffffffu, sum, o);
    if (lane == 0) sred[wid] = sum;
    __syncthreads();
    sum = sred[0];
#pragma unroll
    for (int i = 1; i < 8; i++) sum += sred[i];
    float inv = 1.0f / sum;
    cnt = 0;
    for (int j = tid; j < np; j += 256) {
        float a = lv[cnt].x * inv, b = lv[cnt].y * inv;
        cnt++;
        __half ha, la, hb, lb;
        split1(a, ha, la); split1(b, hb, lb);
        unsigned hw = (unsigned)__half_as_ushort(ha) | ((unsigned)__half_as_ushort(hb) << 16);
        unsigned lw = (unsigned)__half_as_ushort(la) | ((unsigned)__half_as_ushort(lb) << 16);
        *(unsigned*)(dst + 2ll * j) = hw;
        *(unsigned*)(dst + plane + 2ll * j) = lw;
    }
}

// ---------------- merge + bbox mask -> fp16 planes ----------------
__global__ void merge_img_b(const float* __restrict__ O, const float* __restrict__ ipO,
                            __half* __restrict__ dst)
{
    int l = blockIdx.x, h = blockIdx.y, d = threadIdx.x;
    int row = l >> 5, col = l & 31;
    float m = (row >= 8 && row < 24 && col >= 8 && col < 24) ? 1.0f : 0.0f;
    float res = O[((long long)h * SALL + TXT_ + l) * DHD + d] +
                m * ipO[((long long)h * IMG_ + l) * DHD + d];
    __half hh, ll;
    split1(res, hh, ll);
    long long idx = (long long)l * HID_ + h * DHD + d;
    dst[idx] = hh;
    dst[idx + PIMG] = ll;
}

__global__ void merge_enc_b(const float* __restrict__ O, __half* __restrict__ dst)
{
    int s = blockIdx.x, h = blockIdx.y, d = threadIdx.x;
    float res = O[((long long)h * SALL + s) * DHD + d];
    __half hh, ll;
    split1(res, hh, ll);
    long long idx = (long long)s * HID_ + h * DHD + d;
    dst[idx] = hh;
    dst[idx + PENC] = ll;
}

// ---------------- launch ----------------
extern "C" void kernel_launch(void* const* d_in, const int* in_sizes, int n_in,
                              void* d_out, int out_size)
{
    const float* hidden   = (const float*)d_in[0];
    const float* enc_hs   = (const float*)d_in[1];
    const float* ip_hs    = (const float*)d_in[2];
    const float* rope_cos = (const float*)d_in[3];
    const float* rope_sin = (const float*)d_in[4];
    const float* Wq  = (const float*)d_in[5];
    const float* bq  = (const float*)d_in[6];
    const float* Wk  = (const float*)d_in[7];
    const float* bk  = (const float*)d_in[8];
    const float* Wv  = (const float*)d_in[9];
    const float* bv  = (const float*)d_in[10];
    const float* norm_q_w = (const float*)d_in[11];
    const float* norm_k_w = (const float*)d_in[12];
    const float* Wq_add = (const float*)d_in[13];
    const float* bq_add = (const float*)d_in[14];
    const float* Wk_add = (const float*)d_in[15];
    const float* bk_add = (const float*)d_in[16];
    const float* Wv_add = (const float*)d_in[17];
    const float* bv_add = (const float*)d_in[18];
    const float* norm_added_q_w = (const float*)d_in[19];
    const float* norm_added_k_w = (const float*)d_in[20];
    const float* W_out = (const float*)d_in[21];
    const float* b_out = (const float*)d_in[22];
    const float* W_add_out = (const float*)d_in[23];
    const float* b_add_out = (const float*)d_in[24];
    const float* W_k_ip = (const float*)d_in[25];
    const float* b_k_ip = (const float*)d_in[26];
    const float* W_v_ip = (const float*)d_in[27];
    const float* b_v_ip = (const float*)d_in[28];
    const float* norm_ip_q_w = (const float*)d_in[29];
    const float* norm_ip_k_w = (const float*)d_in[30];

    float* out_img = (float*)d_out;
    float* out_enc = out_img + (size_t)IMG_ * HID_;

    float *qkv, *eqkv, *ipkv, *Sb, *Sip, *O, *ipO, *bqkv, *beqkv, *bip;
    __half *hb, *eb, *ipb, *Wqkvb, *Weqkvb, *Wipb, *Wob, *Waob;
    __half *qfb, *kfb, *vtb, *Pb, *Sipb, *ipqb, *ipkb, *ipvtb, *imgb, *encb;
    cudaGetSymbolAddress((void**)&qkv, g_qkv);
    cudaGetSymbolAddress((void**)&eqkv, g_eqkv);
    cudaGetSymbolAddress((void**)&ipkv, g_ipkv);
    cudaGetSymbolAddress((void**)&Sb, g_S);
    cudaGetSymbolAddress((void**)&Sip, g_Sip);
    cudaGetSymbolAddress((void**)&O, g_O);
    cudaGetSymbolAddress((void**)&ipO, g_ipO);
    cudaGetSymbolAddress((void**)&bqkv, g_bqkv);
    cudaGetSymbolAddress((void**)&beqkv, g_beqkv);
    cudaGetSymbolAddress((void**)&bip, g_bip);
    cudaGetSymbolAddress((void**)&hb, g_hb);
    cudaGetSymbolAddress((void**)&eb, g_eb);
    cudaGetSymbolAddress((void**)&ipb, g_ipb);
    cudaGetSymbolAddress((void**)&Wqkvb, g_Wqkv_b);
    cudaGetSymbolAddress((void**)&Weqkvb, g_Weqkv_b);
    cudaGetSymbolAddress((void**)&Wipb, g_Wip_b);
    cudaGetSymbolAddress((void**)&Wob, g_Wo_b);
    cudaGetSymbolAddress((void**)&Waob, g_Wao_b);
    cudaGetSymbolAddress((void**)&qfb, g_qf_b);
    cudaGetSymbolAddress((void**)&kfb, g_kf_b);
    cudaGetSymbolAddress((void**)&vtb, g_vt_b);
    cudaGetSymbolAddress((void**)&Pb, g_P_b);
    cudaGetSymbolAddress((void**)&Sipb, g_Sip_b);
    cudaGetSymbolAddress((void**)&ipqb, g_ipq_b);
    cudaGetSymbolAddress((void**)&ipkb, g_ipk_b);
    cudaGetSymbolAddress((void**)&ipvtb, g_ipvt_b);
    cudaGetSymbolAddress((void**)&imgb, g_img_b);
    cudaGetSymbolAddress((void**)&encb, g_enc_b);

    cudaFuncSetAttribute(gemm_tc<2>, cudaFuncAttributeMaxDynamicSharedMemorySize, GSM);
    cudaFuncSetAttribute(gemm_tc<3>, cudaFuncAttributeMaxDynamicSharedMemorySize, GSM);

    const float scale = 0.08838834764831845f; // 1/sqrt(128)
    const int WW4 = PW / 4, WIP4 = (HID_ * IPD_) / 4;
    const long long WWE = (long long)PW;
    const long long WIPE = (long long)HID_ * IPD_;

    // --- pack inputs & weights into fused hi/lo planes ---
    pack_split<<<(PH / 4 + 255) / 256, 256>>>(hidden, hb, PH, PH / 4);
    pack_split<<<(PE / 4 + 255) / 256, 256>>>(enc_hs, eb, PE, PE / 4);
    pack_split<<<(PIP / 4 + 255) / 256, 256>>>(ip_hs, ipb, PIP, PIP / 4);
    pack_split<<<(WW4 + 255) / 256, 256>>>(Wq, Wqkvb, PW3, WW4);
    pack_split<<<(WW4 + 255) / 256, 256>>>(Wk, Wqkvb + WWE, PW3, WW4);
    pack_split<<<(WW4 + 255) / 256, 256>>>(Wv, Wqkvb + 2 * WWE, PW3, WW4);
    pack_split<<<(WW4 + 255) / 256, 256>>>(Wq_add, Weqkvb, PW3, WW4);
    pack_split<<<(WW4 + 255) / 256, 256>>>(Wk_add, Weqkvb + WWE, PW3, WW4);
    pack_split<<<(WW4 + 255) / 256, 256>>>(Wv_add, Weqkvb + 2 * WWE, PW3, WW4);
    pack_split<<<(WIP4 + 255) / 256, 256>>>(W_k_ip, Wipb, PW2, WIP4);
    pack_split<<<(WIP4 + 255) / 256, 256>>>(W_v_ip, Wipb + WIPE, PW2, WIP4);
    pack_split<<<(WW4 + 255) / 256, 256>>>(W_out, Wob, PW, WW4);
    pack_split<<<(WW4 + 255) / 256, 256>>>(W_add_out, Waob, PW, WW4);
    concat3<<<(N3 + 255) / 256, 256>>>(bq, bk, bv, bqkv, HID_);
    concat3<<<(N3 + 255) / 256, 256>>>(bq_add, bk_add, bv_add, beqkv, HID_);
    concat2<<<(N2 + 255) / 256, 256>>>(b_k_ip, b_v_ip, bip, HID_);

    // --- fused projections (2-term) ---
    gemm_tc<2><<<dim3(N3 / 128, IMG_ / 128), 256, GSM>>>(hb, PH, Wqkvb, PW3, bqkv, qkv, IMG_, N3, HID_, 0, 0, 0);
    gemm_tc<2><<<dim3(N3 / 128, TXT_ / 128), 256, GSM>>>(eb, PE, Weqkvb, PW3, beqkv, eqkv, TXT_, N3, HID_, 0, 0, 0);
    gemm_tc<2><<<dim3(N2 / 128, IPL_ / 128), 256, GSM>>>(ipb, PIP, Wipb, PW2, bip, ipkv, IPL_, N2, IPD_, 0, 0, 0);

    // --- heads / rms / rope / transposes (write planes) ---
    build_qk_rope<<<dim3(SALL, HN), 128>>>(eqkv, qkv, norm_added_q_w, norm_q_w, rope_cos, rope_sin, qfb);
    build_qk_rope<<<dim3(SALL, HN), 128>>>(eqkv + HID_, qkv + HID_, norm_added_k_w, norm_k_w, rope_cos, rope_sin, kfb);
    transpose_heads_b<<<dim3(SALL / 32, DHD / 32, HN), dim3(32, 8)>>>(eqkv + 2 * HID_, qkv + 2 * HID_, N3, TXT_, vtb, SALL, PVT);
    build_rms<<<dim3(IMG_, HN), 128>>>(qkv, N3, norm_ip_q_w, ipqb, IMG_, PIPQ);
    build_rms<<<dim3(IPL_, HN), 128>>>(ipkv, N2, norm_ip_k_w, ipkb, IPL_, PIPK);
    transpose_heads_b<<<dim3(IPL_ / 32, DHD / 32, HN), dim3(32, 8)>>>(ipkv + HID_, ipkv + HID_, N2, IPL_, ipvtb, IPL_, PIPVT);

    // --- main attention (QK 3-term; PV 2-term) ---
    gemm_tc<3><<<dim3(SALL / 128, SALL / 128, HN), 256, GSM>>>(
        qfb, PQF, kfb, PQF, nullptr, Sb, SALL, SALL, DHD,
        (long long)SALL * DHD, (long long)SALL * DHD, (long long)SALL * SALL);
    softmax_b<<<HN * SALL, 256>>>(Sb, Pb, SALL, scale, PPR);
    gemm_tc<2><<<dim3(DHD / 128, SALL / 128, HN), 256, GSM>>>(
        Pb, PPR, vtb, PVT, nullptr, O, SALL, DHD, SALL,
        (long long)SALL * SALL, (long long)DHD * SALL, (long long)SALL * DHD);

    // --- ip attention ---
    gemm_tc<3><<<dim3(IPL_ / 128, IMG_ / 128, HN), 256, GSM>>>(
        ipqb, PIPQ, ipkb, PIPK, nullptr, Sip, IMG_, IPL_, DHD,
        (long long)IMG_ * DHD, (long long)IPL_ * DHD, (long long)IMG_ * IPL_);
    softmax_b<<<HN * IMG_, 256>>>(Sip, Sipb, IPL_, scale, PSIP);
    gemm_tc<2><<<dim3(DHD / 128, IMG_ / 128, HN), 256, GSM>>>(
        Sipb, PSIP, ipvtb, PIPVT, nullptr, ipO, IMG_, DHD, IPL_,
        (long long)IMG_ * IPL_, (long long)DHD * IPL_, (long long)IMG_ * DHD);

    // --- merge + output projections (2-term) ---
    merge_img_b<<<dim3(IMG_, HN), 128>>>(O, ipO, imgb);
    merge_enc_b<<<dim3(TXT_, HN), 128>>>(O, encb);
    gemm_tc<2><<<dim3(HID_ / 128, IMG_ / 128), 256, GSM>>>(imgb, PIMG, Wob, PW, b_out, out_img, IMG_, HID_, HID_, 0, 0, 0);
    gemm_tc<2><<<dim3(HID_ / 128, TXT_ / 128), 256, GSM>>>(encb, PENC, Waob, PW, b_add_out, out_enc, TXT_, HID_, HID_, 0, 0, 0);
}

// round 13
// speedup vs baseline: 2.1894x; 1.0403x over previous
#include <cuda_runtime.h>
#include <cuda_fp16.h>
#include <math.h>
#include <stdint.h>

#define HN   24
#define DHD  128
#define TXT_ 512
#define IMG_ 1024
#define SALL 1536
#define HID_ 3072
#define IPD_ 1152
#define IPL_ 128
#define N3   (3 * HID_)
#define N2   (2 * HID_)

// plane sizes (elements per hi plane; lo plane at +plane where present)
#define PH    (IMG_ * HID_)
#define PE    (TXT_ * HID_)
#define PIP   (IPL_ * IPD_)
#define PW    (HID_ * HID_)
#define PW3   (N3 * HID_)
#define PW2   (N2 * IPD_)
#define PQF   (HN * SALL * DHD)
#define PVT   (HN * DHD * SALL)
#define PPR   (HN * SALL * SALL)
#define PSIP  (HN * IMG_ * IPL_)
#define PIPQ  (HN * IMG_ * DHD)
#define PIPK  (HN * IPL_ * DHD)
#define PIPVT (HN * DHD * IPL_)
#define PIMG  (IMG_ * HID_)
#define PENC  (TXT_ * HID_)

// ---------------- static scratch ----------------
__device__ float g_qkv[IMG_ * N3];
__device__ float g_eqkv[TXT_ * N3];
__device__ float g_ipkv[IPL_ * N2];
__device__ float g_S[HN * SALL * SALL];
__device__ float g_Sip[HN * IMG_ * IPL_];
__device__ float g_O[HN * SALL * DHD];
__device__ float g_ipO[HN * IMG_ * DHD];
__device__ float g_bqkv[N3];
__device__ float g_beqkv[N3];
__device__ float g_bip[N2];
// fp16 planes (hi, and lo at +plane for A-side / 3-term operands)
__device__ __half g_hb[2 * PH];
__device__ __half g_eb[2 * PE];
__device__ __half g_ipb[2 * PIP];
__device__ __half g_Wqkv_b[PW3];       // hi only (B of 2-term)
__device__ __half g_Weqkv_b[PW3];      // hi only
__device__ __half g_Wip_b[PW2];        // hi only
__device__ __half g_Wo_b[PW];          // hi only
__device__ __half g_Wao_b[PW];         // hi only
__device__ __half g_qf_b[2 * PQF];
__device__ __half g_kf_b[2 * PQF];
__device__ __half g_vt_b[PVT];         // hi only (B of 2-term PV)
__device__ __half g_P_b[2 * PPR];
__device__ __half g_Sip_b[2 * PSIP];
__device__ __half g_ipq_b[2 * PIPQ];
__device__ __half g_ipk_b[2 * PIPK];
__device__ __half g_ipvt_b[PIPVT];     // hi only
__device__ __half g_img_b[2 * PIMG];
__device__ __half g_enc_b[2 * PENC];

// ---------------- helpers ----------------
__device__ __forceinline__ void split1(float x, __half& h, __half& l) {
    h = __float2half_rn(x);
    l = __float2half_rn(x - __half2float(h));
}

__device__ __forceinline__ void mma_f16(float* d, const unsigned* a, const unsigned* b) {
    asm volatile(
        "mma.sync.aligned.m16n8k16.row.col.f32.f16.f16.f32 "
        "{%0,%1,%2,%3}, {%4,%5,%6,%7}, {%8,%9}, {%0,%1,%2,%3};"
        : "+f"(d[0]), "+f"(d[1]), "+f"(d[2]), "+f"(d[3])
        : "r"(a[0]), "r"(a[1]), "r"(a[2]), "r"(a[3]), "r"(b[0]), "r"(b[1]));
}

__device__ __forceinline__ void ldsm4(uint32_t addr, unsigned* r) {
    asm volatile("ldmatrix.sync.aligned.m8n8.x4.shared.b16 {%0,%1,%2,%3}, [%4];"
        : "=r"(r[0]), "=r"(r[1]), "=r"(r[2]), "=r"(r[3]) : "r"(addr));
}

__device__ __forceinline__ void cpa16(uint32_t dst, const void* src) {
    asm volatile("cp.async.cg.shared.global [%0], [%1], 16;" :: "r"(dst), "l"(src));
}
__device__ __forceinline__ void cp_commit() {
    asm volatile("cp.async.commit_group;" ::: "memory");
}
template <int NN>
__device__ __forceinline__ void cp_wait() {
    asm volatile("cp.async.wait_group %0;" :: "n"(NN) : "memory");
}

// ---------------- fp16 split GEMM (NT, planes, ldmatrix, cp.async x3) -------
// C[M,N] = A[M,K]*B[N,K]^T + bias. A hi at A, lo at A+loA. BK=32.
// TERMS==2: ah*bh + al*bh  (B hi-only; loB unused)
// TERMS==3: ah*bh + al*bh + ah*bl (B hi+lo at B+loB)
// BM=128, BN=128, 256 threads, 8 warps (4x2), warp 32x64.
#define GST   3
#define STGB  32768
#define GSM   (GST * STGB)

template <int TERMS>
__global__ __launch_bounds__(256, 2) void gemm_tc(
    const __half* __restrict__ A, long long loA,
    const __half* __restrict__ B, long long loB,
    const float* __restrict__ bias, float* __restrict__ C,
    int M, int N, int K,
    long long sA, long long sB, long long sC)
{
    A += (long long)blockIdx.z * sA;
    B += (long long)blockIdx.z * sB;
    C += (long long)blockIdx.z * sC;

    extern __shared__ __align__(16) char smem[];
    uint32_t sb = (uint32_t)__cvta_generic_to_shared(smem);

    int tid = threadIdx.x;
    int warp = tid >> 5, lane = tid & 31;
    int wm = warp >> 1, wn = warp & 1;
    int m0 = blockIdx.y * 128, n0 = blockIdx.x * 128;
    int g = lane >> 2, t = lane & 3;
    int l7 = lane & 7, l8 = (lane >> 3) & 1, kh = lane >> 4;

    float acc[2][8][4];
#pragma unroll
    for (int mt = 0; mt < 2; mt++)
#pragma unroll
        for (int nt = 0; nt < 8; nt++)
#pragma unroll
            for (int i = 0; i < 4; i++) acc[mt][nt][i] = 0.f;

    int nkt = K >> 5;

#define LOAD_STAGE(kt, s)                                                                \
    {                                                                                    \
        int kb = (kt) << 5;                                                              \
        uint32_t ab = sb + (s) * STGB;                                                   \
        uint32_t bb = ab + 16384;                                                        \
        _Pragma("unroll")                                                                \
        for (int it = 0; it < 4; it++) {                                                 \
            int idx = tid + it * 256;                                                    \
            int row = idx >> 3, c8 = idx & 7;                                            \
            int pl = c8 >> 2, c = c8 & 3;                                                \
            cpa16(ab + row * 128 + ((c8 ^ (row & 7)) << 4),                              \
                  A + (long long)pl * loA + (long long)(m0 + row) * K + kb + c * 8);     \
        }                                                                                \
        _Pragma("unroll")                                                                \
        for (int it = 0; it < 4; it++) {                                                 \
            int idx = tid + it * 256;                                                    \
            int row = idx >> 3, c8 = idx & 7;                                            \
            int pl = c8 >> 2, c = c8 & 3;                                                \
            if (TERMS == 3 || pl == 0)                                                   \
                cpa16(bb + row * 128 + ((c8 ^ (row & 7)) << 4),                          \
                      B + (long long)pl * loB + (long long)(n0 + row) * K + kb + c * 8); \
        }                                                                                \
    }

    LOAD_STAGE(0, 0);
    cp_commit();
    if (nkt > 1) { LOAD_STAGE(1, 1); }
    cp_commit();

    for (int kt = 0; kt < nkt; kt++) {
        cp_wait<1>();
        __syncthreads();
        if (kt + 2 < nkt) {
            int s = (kt + 2) % GST;
            LOAD_STAGE(kt + 2, s);
        }
        cp_commit();

        uint32_t sA_ = sb + (kt % GST) * STGB;
        uint32_t sB_ = sA_ + 16384;

#pragma unroll
        for (int kc = 0; kc < 2; kc++) {
            int chunk = kc * 2 + kh;                  // 0..3
            unsigned ah[2][4], al[2][4];
#pragma unroll
            for (int mt = 0; mt < 2; mt++) {
                int row = wm * 32 + mt * 16 + l7 + l8 * 8;
                uint32_t base = sA_ + row * 128;
                ldsm4(base + ((chunk ^ (row & 7)) << 4), ah[mt]);
                ldsm4(base + (((chunk + 4) ^ (row & 7)) << 4), al[mt]);
            }
#pragma unroll
            for (int np = 0; np < 4; np++) {
                int row = wn * 64 + np * 16 + l7 + l8 * 8;
                uint32_t base = sB_ + row * 128;
                unsigned bh4[4], bl4[4];
                ldsm4(base + ((chunk ^ (row & 7)) << 4), bh4);
                if (TERMS == 3)
                    ldsm4(base + (((chunk + 4) ^ (row & 7)) << 4), bl4);
#pragma unroll
                for (int sub = 0; sub < 2; sub++) {
                    int nt = np * 2 + sub;
                    unsigned bh[2] = { bh4[sub], bh4[sub + 2] };
#pragma unroll
                    for (int mt = 0; mt < 2; mt++) {
                        mma_f16(acc[mt][nt], ah[mt], bh);
                        mma_f16(acc[mt][nt], al[mt], bh);
                        if (TERMS == 3) {
                            unsigned bl[2] = { bl4[sub], bl4[sub + 2] };
                            mma_f16(acc[mt][nt], ah[mt], bl);
                        }
                    }
                }
            }
        }
    }

#pragma unroll
    for (int nt = 0; nt < 8; nt++) {
        int ncol = n0 + wn * 64 + nt * 8 + t * 2;
        float2 bv;
        if (bias) bv = *(const float2*)(bias + ncol);
        else { bv.x = 0.f; bv.y = 0.f; }
#pragma unroll
        for (int mt = 0; mt < 2; mt++) {
            int mrow = m0 + wm * 32 + mt * 16 + g;
            float2 v0, v1;
            v0.x = acc[mt][nt][0] + bv.x; v0.y = acc[mt][nt][1] + bv.y;
            v1.x = acc[mt][nt][2] + bv.x; v1.y = acc[mt][nt][3] + bv.y;
            *(float2*)(C + (long long)mrow * N + ncol) = v0;
            *(float2*)(C + (long long)(mrow + 8) * N + ncol) = v1;
        }
    }
}

// ---------------- pack: fp32 -> fp16 hi/lo planes ----------------
__global__ void pack_split(const float* __restrict__ src, __half* __restrict__ dst,
                           long long plane, int n4) {
    int i = blockIdx.x * 256 + threadIdx.x;
    if (i < n4) {
        float4 f = ((const float4*)src)[i];
        __half h0, h1, h2, h3, l0, l1, l2, l3;
        split1(f.x, h0, l0); split1(f.y, h1, l1);
        split1(f.z, h2, l2); split1(f.w, h3, l3);
        uint2 hi, lo;
        hi.x = (unsigned)__half_as_ushort(h0) | ((unsigned)__half_as_ushort(h1) << 16);
        hi.y = (unsigned)__half_as_ushort(h2) | ((unsigned)__half_as_ushort(h3) << 16);
        lo.x = (unsigned)__half_as_ushort(l0) | ((unsigned)__half_as_ushort(l1) << 16);
        lo.y = (unsigned)__half_as_ushort(l2) | ((unsigned)__half_as_ushort(l3) << 16);
        *(uint2*)(dst + 4ll * i) = hi;
        *(uint2*)(dst + plane + 4ll * i) = lo;
    }
}

// fp32 -> fp16 hi plane only (for B-side of 2-term GEMMs)
__global__ void pack_hi(const float* __restrict__ src, __half* __restrict__ dst, int n4) {
    int i = blockIdx.x * 256 + threadIdx.x;
    if (i < n4) {
        float4 f = ((const float4*)src)[i];
        uint2 hi;
        hi.x = (unsigned)__half_as_ushort(__float2half_rn(f.x)) |
               ((unsigned)__half_as_ushort(__float2half_rn(f.y)) << 16);
        hi.y = (unsigned)__half_as_ushort(__float2half_rn(f.z)) |
               ((unsigned)__half_as_ushort(__float2half_rn(f.w)) << 16);
        *(uint2*)(dst + 4ll * i) = hi;
    }
}

// ---------------- bias concat ----------------
__global__ void concat3(const float* __restrict__ a, const float* __restrict__ b,
                        const float* __restrict__ c, float* __restrict__ d, int n) {
    int i = blockIdx.x * 256 + threadIdx.x;
    if (i < n) d[i] = a[i];
    else if (i < 2 * n) d[i] = b[i - n];
    else if (i < 3 * n) d[i] = c[i - 2 * n];
}
__global__ void concat2(const float* __restrict__ a, const float* __restrict__ b,
                        float* __restrict__ d, int n) {
    int i = blockIdx.x * 256 + threadIdx.x;
    if (i < n) d[i] = a[i];
    else if (i < 2 * n) d[i] = b[i - n];
}

// ---------------- heads + RMS + RoPE -> fp16 planes (hi+lo) ----------------
__global__ void build_qk_rope(const float* __restrict__ enc_src,
                              const float* __restrict__ img_src,
                              const float* __restrict__ w_enc,
                              const float* __restrict__ w_img,
                              const float* __restrict__ cosb,
                              const float* __restrict__ sinb,
                              __half* __restrict__ dst)
{
    int s = blockIdx.x, h = blockIdx.y, d = threadIdx.x;
    const float* src;
    const float* w;
    if (s < TXT_) { src = enc_src + (long long)s * N3; w = w_enc; }
    else          { src = img_src + (long long)(s - TXT_) * N3; w = w_img; }
    float x = src[h * DHD + d];
    float ss = x * x;
#pragma unroll
    for (int o = 16; o; o >>= 1) ss += __shfl_xor_sync(0xffffffffu, ss, o);
    __shared__ float sred[4];
    int lane = d & 31, wid = d >> 5;
    if (lane == 0) sred[wid] = ss;
    __syncthreads();
    ss = sred[0] + sred[1] + sred[2] + sred[3];
    float r = rsqrtf(ss * (1.0f / DHD) + 1e-6f);
    float xn = x * r * w[d];
    float partner = __shfl_xor_sync(0xffffffffu, xn, 1);
    float rot = (d & 1) ? partner : -partner;
    long long si = (long long)s * DHD + d;
    float res = xn * cosb[si] + rot * sinb[si];
    __half hh, ll;
    split1(res, hh, ll);
    long long idx = ((long long)h * SALL + s) * DHD + d;
    dst[idx] = hh;
    dst[idx + PQF] = ll;
}

// rms -> fp16 planes (hi+lo) dst[h][s][d]
__global__ void build_rms(const float* __restrict__ src, int stride,
                          const float* __restrict__ w,
                          __half* __restrict__ dst, int Srows, long long plane)
{
    int s = blockIdx.x, h = blockIdx.y, d = threadIdx.x;
    float x = src[(long long)s * stride + h * DHD + d];
    float ss = x * x;
#pragma unroll
    for (int o = 16; o; o >>= 1) ss += __shfl_xor_sync(0xffffffffu, ss, o);
    __shared__ float sred[4];
    int lane = d & 31, wid = d >> 5;
    if (lane == 0) sred[wid] = ss;
    __syncthreads();
    ss = sred[0] + sred[1] + sred[2] + sred[3];
    float r = rsqrtf(ss * (1.0f / DHD) + 1e-6f);
    float res = x * r * w[d];
    __half hh, ll;
    split1(res, hh, ll);
    long long idx = ((long long)h * Srows + s) * DHD + d;
    dst[idx] = hh;
    dst[idx + plane] = ll;
}

// transpose to fp16 hi-only dst[h][d][s]. block (32,8), grid (S/32, DHD/32, HN)
__global__ void transpose_heads_hi(const float* __restrict__ enc, const float* __restrict__ img,
                                   int stride, int ntxt, __half* __restrict__ dst, int Srows)
{
    __shared__ float tbuf[32][33];
    int s0 = blockIdx.x * 32, d0 = blockIdx.y * 32, h = blockIdx.z;
    int tx = threadIdx.x, ty = threadIdx.y;
#pragma unroll
    for (int j = 0; j < 4; j++) {
        int s = s0 + ty + j * 8;
        const float* src = (s < ntxt) ? enc + (long long)s * stride
                                      : img + (long long)(s - ntxt) * stride;
        tbuf[ty + j * 8][tx] = src[h * DHD + d0 + tx];
    }
    __syncthreads();
#pragma unroll
    for (int j = 0; j < 4; j++) {
        int dl = ty + j * 8;
        int d = d0 + dl;
        dst[((long long)h * DHD + d) * Srows + s0 + tx] = __float2half_rn(tbuf[tx][dl]);
    }
}

// ---------------- softmax: fp32 in -> fp16 hi/lo planes out ----------------
__global__ void softmax_b(const float* __restrict__ S, __half* __restrict__ P,
                          int ncols, float scale, long long plane)
{
    long long row = blockIdx.x;
    const float* src = S + row * (long long)ncols;
    __half* dst = P + row * (long long)ncols;
    int tid = threadIdx.x;
    int np = ncols >> 1;
    float2 lv[3];
    int cnt = 0;
    float mx = -INFINITY;
    for (int j = tid; j < np; j += 256) {
        float2 v = ((const float2*)src)[j];
        v.x *= scale; v.y *= scale;
        lv[cnt++] = v;
        mx = fmaxf(mx, fmaxf(v.x, v.y));
    }
    __shared__ float sred[8];
    int lane = tid & 31, wid = tid >> 5;
#pragma unroll
    for (int o = 16; o; o >>= 1) mx = fmaxf(mx, __shfl_xor_sync(0xffffffffu, mx, o));
    if (lane == 0) sred[wid] = mx;
    __syncthreads();
    mx = sred[0];
#pragma unroll
    for (int i = 1; i < 8; i++) mx = fmaxf(mx, sred[i]);
    __syncthreads();
    float sum = 0.f;
    for (int c = 0; c < cnt; c++) {
        lv[c].x = expf(lv[c].x - mx);
        lv[c].y = expf(lv[c].y - mx);
        sum += lv[c].x + lv[c].y;
    }
#pragma unroll
    for (int o = 16; o; o >>= 1) sum += __shfl_xor_sync(0xffffffffu, sum, o);
    if (lane == 0) sred[wid] = sum;
    __syncthreads();
    sum = sred[0];
#pragma unroll
    for (int i = 1; i < 8; i++) sum += sred[i];
    float inv = 1.0f / sum;
    cnt = 0;
    for (int j = tid; j < np; j += 256) {
        float a = lv[cnt].x * inv, b = lv[cnt].y * inv;
        cnt++;
        __half ha, la, hb, lb;
        split1(a, ha, la); split1(b, hb, lb);
        unsigned hw = (unsigned)__half_as_ushort(ha) | ((unsigned)__half_as_ushort(hb) << 16);
        unsigned lw = (unsigned)__half_as_ushort(la) | ((unsigned)__half_as_ushort(lb) << 16);
        *(unsigned*)(dst + 2ll * j) = hw;
        *(unsigned*)(dst + plane + 2ll * j) = lw;
    }
}

// ---------------- merge + bbox mask -> fp16 planes (hi+lo) ----------------
__global__ void merge_img_b(const float* __restrict__ O, const float* __restrict__ ipO,
                            __half* __restrict__ dst)
{
    int l = blockIdx.x, h = blockIdx.y, d = threadIdx.x;
    int row = l >> 5, col = l & 31;
    float m = (row >= 8 && row < 24 && col >= 8 && col < 24) ? 1.0f : 0.0f;
    float res = O[((long long)h * SALL + TXT_ + l) * DHD + d] +
                m * ipO[((long long)h * IMG_ + l) * DHD + d];
    __half hh, ll;
    split1(res, hh, ll);
    long long idx = (long long)l * HID_ + h * DHD + d;
    dst[idx] = hh;
    dst[idx + PIMG] = ll;
}

__global__ void merge_enc_b(const float* __restrict__ O, __half* __restrict__ dst)
{
    int s = blockIdx.x, h = blockIdx.y, d = threadIdx.x;
    float res = O[((long long)h * SALL + s) * DHD + d];
    __half hh, ll;
    split1(res, hh, ll);
    long long idx = (long long)s * HID_ + h * DHD + d;
    dst[idx] = hh;
    dst[idx + PENC] = ll;
}

// ---------------- launch ----------------
extern "C" void kernel_launch(void* const* d_in, const int* in_sizes, int n_in,
                              void* d_out, int out_size)
{
    const float* hidden   = (const float*)d_in[0];
    const float* enc_hs   = (const float*)d_in[1];
    const float* ip_hs    = (const float*)d_in[2];
    const float* rope_cos = (const float*)d_in[3];
    const float* rope_sin = (const float*)d_in[4];
    const float* Wq  = (const float*)d_in[5];
    const float* bq  = (const float*)d_in[6];
    const float* Wk  = (const float*)d_in[7];
    const float* bk  = (const float*)d_in[8];
    const float* Wv  = (const float*)d_in[9];
    const float* bv  = (const float*)d_in[10];
    const float* norm_q_w = (const float*)d_in[11];
    const float* norm_k_w = (const float*)d_in[12];
    const float* Wq_add = (const float*)d_in[13];
    const float* bq_add = (const float*)d_in[14];
    const float* Wk_add = (const float*)d_in[15];
    const float* bk_add = (const float*)d_in[16];
    const float* Wv_add = (const float*)d_in[17];
    const float* bv_add = (const float*)d_in[18];
    const float* norm_added_q_w = (const float*)d_in[19];
    const float* norm_added_k_w = (const float*)d_in[20];
    const float* W_out = (const float*)d_in[21];
    const float* b_out = (const float*)d_in[22];
    const float* W_add_out = (const float*)d_in[23];
    const float* b_add_out = (const float*)d_in[24];
    const float* W_k_ip = (const float*)d_in[25];
    const float* b_k_ip = (const float*)d_in[26];
    const float* W_v_ip = (const float*)d_in[27];
    const float* b_v_ip = (const float*)d_in[28];
    const float* norm_ip_q_w = (const float*)d_in[29];
    const float* norm_ip_k_w = (const float*)d_in[30];

    float* out_img = (float*)d_out;
    float* out_enc = out_img + (size_t)IMG_ * HID_;

    float *qkv, *eqkv, *ipkv, *Sb, *Sip, *O, *ipO, *bqkv, *beqkv, *bip;
    __half *hb, *eb, *ipb, *Wqkvb, *Weqkvb, *Wipb, *Wob, *Waob;
    __half *qfb, *kfb, *vtb, *Pb, *Sipb, *ipqb, *ipkb, *ipvtb, *imgb, *encb;
    cudaGetSymbolAddress((void**)&qkv, g_qkv);
    cudaGetSymbolAddress((void**)&eqkv, g_eqkv);
    cudaGetSymbolAddress((void**)&ipkv, g_ipkv);
    cudaGetSymbolAddress((void**)&Sb, g_S);
    cudaGetSymbolAddress((void**)&Sip, g_Sip);
    cudaGetSymbolAddress((void**)&O, g_O);
    cudaGetSymbolAddress((void**)&ipO, g_ipO);
    cudaGetSymbolAddress((void**)&bqkv, g_bqkv);
    cudaGetSymbolAddress((void**)&beqkv, g_beqkv);
    cudaGetSymbolAddress((void**)&bip, g_bip);
    cudaGetSymbolAddress((void**)&hb, g_hb);
    cudaGetSymbolAddress((void**)&eb, g_eb);
    cudaGetSymbolAddress((void**)&ipb, g_ipb);
    cudaGetSymbolAddress((void**)&Wqkvb, g_Wqkv_b);
    cudaGetSymbolAddress((void**)&Weqkvb, g_Weqkv_b);
    cudaGetSymbolAddress((void**)&Wipb, g_Wip_b);
    cudaGetSymbolAddress((void**)&Wob, g_Wo_b);
    cudaGetSymbolAddress((void**)&Waob, g_Wao_b);
    cudaGetSymbolAddress((void**)&qfb, g_qf_b);
    cudaGetSymbolAddress((void**)&kfb, g_kf_b);
    cudaGetSymbolAddress((void**)&vtb, g_vt_b);
    cudaGetSymbolAddress((void**)&Pb, g_P_b);
    cudaGetSymbolAddress((void**)&Sipb, g_Sip_b);
    cudaGetSymbolAddress((void**)&ipqb, g_ipq_b);
    cudaGetSymbolAddress((void**)&ipkb, g_ipk_b);
    cudaGetSymbolAddress((void**)&ipvtb, g_ipvt_b);
    cudaGetSymbolAddress((void**)&imgb, g_img_b);
    cudaGetSymbolAddress((void**)&encb, g_enc_b);

    cudaFuncSetAttribute(gemm_tc<2>, cudaFuncAttributeMaxDynamicSharedMemorySize, GSM);
    cudaFuncSetAttribute(gemm_tc<3>, cudaFuncAttributeMaxDynamicSharedMemorySize, GSM);

    const float scale = 0.08838834764831845f; // 1/sqrt(128)
    const int WW4 = PW / 4, WIP4 = (HID_ * IPD_) / 4;
    const long long WWE = (long long)PW;
    const long long WIPE = (long long)HID_ * IPD_;

    // ----- side stream + events (fork/join; capture-legal) -----
    cudaStream_t s1;
    cudaStreamCreateWithFlags(&s1, cudaStreamNonBlocking);
    cudaEvent_t eFork, eQkv, eW, eIp;
    cudaEventCreateWithFlags(&eFork, cudaEventDisableTiming);
    cudaEventCreateWithFlags(&eQkv, cudaEventDisableTiming);
    cudaEventCreateWithFlags(&eW, cudaEventDisableTiming);
    cudaEventCreateWithFlags(&eIp, cudaEventDisableTiming);

    cudaEventRecord(eFork, 0);
    cudaStreamWaitEvent(s1, eFork, 0);

    // ----- s1: output-projection weight packs -----
    pack_hi<<<(WW4 + 255) / 256, 256, 0, s1>>>(W_out, Wob, WW4);
    pack_hi<<<(WW4 + 255) / 256, 256, 0, s1>>>(W_add_out, Waob, WW4);
    cudaEventRecord(eW, s1);

    // ----- s1: ip chain pre-work -----
    pack_split<<<(PIP / 4 + 255) / 256, 256, 0, s1>>>(ip_hs, ipb, PIP, PIP / 4);
    pack_hi<<<(WIP4 + 255) / 256, 256, 0, s1>>>(W_k_ip, Wipb, WIP4);
    pack_hi<<<(WIP4 + 255) / 256, 256, 0, s1>>>(W_v_ip, Wipb + WIPE, WIP4);
    concat2<<<(N2 + 255) / 256, 256, 0, s1>>>(b_k_ip, b_v_ip, bip, HID_);
    gemm_tc<2><<<dim3(N2 / 128, IPL_ / 128), 256, GSM, s1>>>(ipb, PIP, Wipb, 0, bip, ipkv, IPL_, N2, IPD_, 0, 0, 0);
    build_rms<<<dim3(IPL_, HN), 128, 0, s1>>>(ipkv, N2, norm_ip_k_w, ipkb, IPL_, PIPK);
    transpose_heads_hi<<<dim3(IPL_ / 32, DHD / 32, HN), dim3(32, 8), 0, s1>>>(ipkv + HID_, ipkv + HID_, N2, IPL_, ipvtb, IPL_);

    // ----- s0: main-chain packs + fused projections -----
    pack_split<<<(PH / 4 + 255) / 256, 256>>>(hidden, hb, PH, PH / 4);
    pack_split<<<(PE / 4 + 255) / 256, 256>>>(enc_hs, eb, PE, PE / 4);
    pack_hi<<<(WW4 + 255) / 256, 256>>>(Wq, Wqkvb, WW4);
    pack_hi<<<(WW4 + 255) / 256, 256>>>(Wk, Wqkvb + WWE, WW4);
    pack_hi<<<(WW4 + 255) / 256, 256>>>(Wv, Wqkvb + 2 * WWE, WW4);
    pack_hi<<<(WW4 + 255) / 256, 256>>>(Wq_add, Weqkvb, WW4);
    pack_hi<<<(WW4 + 255) / 256, 256>>>(Wk_add, Weqkvb + WWE, WW4);
    pack_hi<<<(WW4 + 255) / 256, 256>>>(Wv_add, Weqkvb + 2 * WWE, WW4);
    concat3<<<(N3 + 255) / 256, 256>>>(bq, bk, bv, bqkv, HID_);
    concat3<<<(N3 + 255) / 256, 256>>>(bq_add, bk_add, bv_add, beqkv, HID_);

    gemm_tc<2><<<dim3(N3 / 128, IMG_ / 128), 256, GSM>>>(hb, PH, Wqkvb, 0, bqkv, qkv, IMG_, N3, HID_, 0, 0, 0);
    cudaEventRecord(eQkv, 0);
    gemm_tc<2><<<dim3(N3 / 128, TXT_ / 128), 256, GSM>>>(eb, PE, Weqkvb, 0, beqkv, eqkv, TXT_, N3, HID_, 0, 0, 0);

    // ----- s1: ip attention (needs qkv for ip_q) -----
    cudaStreamWaitEvent(s1, eQkv, 0);
    build_rms<<<dim3(IMG_, HN), 128, 0, s1>>>(qkv, N3, norm_ip_q_w, ipqb, IMG_, PIPQ);
    gemm_tc<3><<<dim3(IPL_ / 128, IMG_ / 128, HN), 256, GSM, s1>>>(
        ipqb, PIPQ, ipkb, PIPK, nullptr, Sip, IMG_, IPL_, DHD,
        (long long)IMG_ * DHD, (long long)IPL_ * DHD, (long long)IMG_ * IPL_);
    softmax_b<<<HN * IMG_, 256, 0, s1>>>(Sip, Sipb, IPL_, scale, PSIP);
    gemm_tc<2><<<dim3(DHD / 128, IMG_ / 128, HN), 256, GSM, s1>>>(
        Sipb, PSIP, ipvtb, 0, nullptr, ipO, IMG_, DHD, IPL_,
        (long long)IMG_ * IPL_, (long long)DHD * IPL_, (long long)IMG_ * DHD);
    cudaEventRecord(eIp, s1);

    // ----- s0: main attention -----
    build_qk_rope<<<dim3(SALL, HN), 128>>>(eqkv, qkv, norm_added_q_w, norm_q_w, rope_cos, rope_sin, qfb);
    build_qk_rope<<<dim3(SALL, HN), 128>>>(eqkv + HID_, qkv + HID_, norm_added_k_w, norm_k_w, rope_cos, rope_sin, kfb);
    transpose_heads_hi<<<dim3(SALL / 32, DHD / 32, HN), dim3(32, 8)>>>(eqkv + 2 * HID_, qkv + 2 * HID_, N3, TXT_, vtb, SALL);

    gemm_tc<3><<<dim3(SALL / 128, SALL / 128, HN), 256, GSM>>>(
        qfb, PQF, kfb, PQF, nullptr, Sb, SALL, SALL, DHD,
        (long long)SALL * DHD, (long long)SALL * DHD, (long long)SALL * SALL);
    softmax_b<<<HN * SALL, 256>>>(Sb, Pb, SALL, scale, PPR);
    gemm_tc<2><<<dim3(DHD / 128, SALL / 128, HN), 256, GSM>>>(
        Pb, PPR, vtb, 0, nullptr, O, SALL, DHD, SALL,
        (long long)SALL * SALL, (long long)DHD * SALL, (long long)SALL * DHD);

    // ----- s0: merges + output projections -----
    merge_enc_b<<<dim3(TXT_, HN), 128>>>(O, encb);
    cudaStreamWaitEvent(0, eW, 0);
    gemm_tc<2><<<dim3(HID_ / 128, TXT_ / 128), 256, GSM>>>(encb, PENC, Waob, 0, b_add_out, out_enc, TXT_, HID_, HID_, 0, 0, 0);

    cudaStreamWaitEvent(0, eIp, 0);
    merge_img_b<<<dim3(IMG_, HN), 128>>>(O, ipO, imgb);
    gemm_tc<2><<<dim3(HID_ / 128, IMG_ / 128), 256, GSM>>>(imgb, PIMG, Wob, 0, b_out, out_img, IMG_, HID_, HID_, 0, 0, 0);
}